// round 1
// baseline (speedup 1.0000x reference)
#include <cuda_runtime.h>
#include <cuda_bf16.h>

// ---------------------------------------------------------------------------
// NonlocalBlock fused: B=4, C=64, H=W=96 (N=9216), Ci=32, COMPRESSION=2 (M=4608)
// out = x + ( softmax(theta @ phi^T) @ g ) @ w_out^T + b_out
// theta = x^T W_theta^T + b ;  phi,g = maxpool2( x^T W^T + b ) along N
// ---------------------------------------------------------------------------

#define BB 4
#define CC 64
#define NN 9216
#define CI 32
#define MM 4608
#define LOG2E 1.44269504088896f

typedef unsigned long long ull;

// scratch (allocation-free rule: __device__ globals)
__device__ float d_theta[(size_t)BB * NN * CI];   // 4.7 MB
__device__ float d_phi[(size_t)BB * MM * CI];     // 2.36 MB
__device__ float d_g[(size_t)BB * MM * CI];       // 2.36 MB

// ---- packed f32x2 helpers (sm_100+) ---------------------------------------
__device__ __forceinline__ ull pk2(float lo, float hi) {
    ull r; asm("mov.b64 %0, {%1,%2};" : "=l"(r) : "f"(lo), "f"(hi)); return r;
}
__device__ __forceinline__ void upk2(ull a, float& lo, float& hi) {
    asm("mov.b64 {%0,%1}, %2;" : "=f"(lo), "=f"(hi) : "l"(a));
}
__device__ __forceinline__ ull fma2(ull a, ull b, ull c) {
    ull d; asm("fma.rn.f32x2 %0, %1, %2, %3;" : "=l"(d) : "l"(a), "l"(b), "l"(c)); return d;
}
__device__ __forceinline__ ull add2(ull a, ull b) {
    ull d; asm("add.rn.f32x2 %0, %1, %2;" : "=l"(d) : "l"(a), "l"(b)); return d;
}
__device__ __forceinline__ ull mul2(ull a, ull b) {
    ull d; asm("mul.rn.f32x2 %0, %1, %2;" : "=l"(d) : "l"(a), "l"(b)); return d;
}

// ---------------------------------------------------------------------------
// Kernel 1: projections + maxpool.  grid = (NN/64, BB), 256 threads.
// Each block: 64 spatial positions of one batch.
// ---------------------------------------------------------------------------
__global__ __launch_bounds__(256, 2)
void proj_kernel(const float* __restrict__ x,
                 const float* __restrict__ wt, const float* __restrict__ bt,
                 const float* __restrict__ wp, const float* __restrict__ bp,
                 const float* __restrict__ wg, const float* __restrict__ bg)
{
    __shared__ float xs[64][65];          // [pos][chan], padded
    __shared__ float wts[64][32];         // transposed [c][ci]
    __shared__ float wps[64][32];
    __shared__ float wgs[64][32];

    const int b  = blockIdx.y;
    const int n0 = blockIdx.x * 64;
    const int tid = threadIdx.x;

    // weights, transposed into smem (coalesced global reads)
    for (int i = tid; i < CI * CC; i += 256) {
        int ci = i >> 6, c = i & 63;      // i = ci*64 + c  (global row-major)
        wts[c][ci] = wt[i];
        wps[c][ci] = wp[i];
        wgs[c][ci] = wg[i];
    }
    // x tile: 64 positions x 64 channels (coalesced along n)
    for (int i = tid; i < 64 * 64; i += 256) {
        int c = i >> 6, nl = i & 63;
        xs[nl][c] = x[((size_t)(b * CC + c)) * NN + n0 + nl];
    }
    __syncthreads();

    const int ci = tid & 31;
    const int g8 = tid >> 5;              // 8 groups, 8 positions each
    const float bth = bt[ci], bph = bp[ci], bgg = bg[ci];

    float prev_p = 0.f, prev_g = 0.f;
    #pragma unroll
    for (int i = 0; i < 8; ++i) {
        const int nl = g8 * 8 + i;
        float at = 0.f, ap = 0.f, ag = 0.f;
        #pragma unroll
        for (int c = 0; c < CC; ++c) {
            const float xv = xs[nl][c];   // warp-broadcast
            at = fmaf(xv, wts[c][ci], at);
            ap = fmaf(xv, wps[c][ci], ap);
            ag = fmaf(xv, wgs[c][ci], ag);
        }
        at += bth; ap += bph; ag += bgg;
        d_theta[((size_t)(b * NN + n0 + nl)) * CI + ci] = at;
        if (i & 1) {
            const int m = (n0 + nl) >> 1;
            d_phi[((size_t)(b * MM + m)) * CI + ci] = fmaxf(prev_p, ap);
            d_g  [((size_t)(b * MM + m)) * CI + ci] = fmaxf(prev_g, ag);
        } else {
            prev_p = ap; prev_g = ag;
        }
    }
}

// ---------------------------------------------------------------------------
// Kernel 2: fused attention + output projection + residual.
// grid = (NN/64, BB), 256 threads. Block owns 64 query rows of one batch.
// Thread layout: r = tid/4 (row 0..63), q = tid%3.. (q = tid&3): 4 threads/row,
// each owns 16 key columns col = 4*j + q (bank-friendly interleave).
// Online softmax across 72 tiles of 64 keys.
// ---------------------------------------------------------------------------
__global__ __launch_bounds__(256, 2)
void attn_kernel(const float* __restrict__ x,
                 const float* __restrict__ w_out,
                 const float* __restrict__ b_out,
                 float* __restrict__ out)
{
    __shared__ float phiS[64][36];        // pad 36: q-interleave -> conflict-free
    __shared__ float gS[64][36];
    __shared__ float woS[64][33];         // [c][ci]

    const int b   = blockIdx.y;
    const int n0  = blockIdx.x * 64;
    const int tid = threadIdx.x;
    const int r   = tid >> 2;
    const int q   = tid & 3;

    // w_out [C][Ci] row-major -> smem
    for (int i = tid; i < CC * CI; i += 256) {
        int c = i >> 5, ci = i & 31;
        woS[c][ci] = w_out[i];
    }

    // theta row -> packed registers (16 x f32x2)
    ull th2[16];
    {
        const float4* tp = (const float4*)(d_theta + ((size_t)(b * NN + n0 + r)) * CI);
        #pragma unroll
        for (int i = 0; i < 8; ++i) {
            float4 v = tp[i];
            th2[2 * i]     = pk2(v.x, v.y);
            th2[2 * i + 1] = pk2(v.z, v.w);
        }
    }

    ull y2[16];
    #pragma unroll
    for (int i = 0; i < 16; ++i) y2[i] = 0ull;   // packed {0,0}
    float run_max = -1e30f, run_sum = 0.f;

    const float* phiB = d_phi + ((size_t)b * MM) * CI;
    const float* gB   = d_g   + ((size_t)b * MM) * CI;

    for (int mt = 0; mt < MM / 64; ++mt) {
        __syncthreads();
        // stage phi & g tiles (2048 floats each)
        {
            const float4* p4 = (const float4*)(phiB + (size_t)mt * 64 * CI);
            const float4* g4 = (const float4*)(gB   + (size_t)mt * 64 * CI);
            #pragma unroll
            for (int i = tid; i < 64 * 8; i += 256) {
                int row = i >> 3, c4 = i & 7;
                float4 v = p4[i];
                *(float4*)&phiS[row][c4 * 4] = v;
                float4 w = g4[i];
                *(float4*)&gS[row][c4 * 4] = w;
            }
        }
        __syncthreads();

        // S = theta_row . phi_col  for 16 cols, packed f32x2 dot
        float s[16];
        #pragma unroll
        for (int j = 0; j < 16; ++j) {
            const int col = 4 * j + q;
            const ull* pr = (const ull*)&phiS[col][0];
            ull a0 = 0ull, a1 = 0ull;
            #pragma unroll
            for (int c2 = 0; c2 < 16; c2 += 2) {
                a0 = fma2(th2[c2],     pr[c2],     a0);
                a1 = fma2(th2[c2 + 1], pr[c2 + 1], a1);
            }
            ull a = add2(a0, a1);
            float lo, hi; upk2(a, lo, hi);
            s[j] = lo + hi;
        }

        // tile max -> row max (reduce across the 4 q-threads of this row)
        float tmax = s[0];
        #pragma unroll
        for (int j = 1; j < 16; ++j) tmax = fmaxf(tmax, s[j]);
        tmax = fmaxf(tmax, __shfl_xor_sync(0xffffffffu, tmax, 1));
        tmax = fmaxf(tmax, __shfl_xor_sync(0xffffffffu, tmax, 2));

        const float nmax  = fmaxf(run_max, tmax);
        const float scale = __expf(run_max - nmax);
        run_max = nmax;
        run_sum *= scale;
        const ull sc2 = pk2(scale, scale);
        #pragma unroll
        for (int i = 0; i < 16; ++i) y2[i] = mul2(y2[i], sc2);

        // P = exp(S - max);  y += P @ g
        #pragma unroll
        for (int j = 0; j < 16; ++j) {
            const int col = 4 * j + q;
            const float p = __expf(s[j] - nmax);
            run_sum += p;
            const ull p2 = pk2(p, p);
            const ull* gr = (const ull*)&gS[col][0];
            #pragma unroll
            for (int c2 = 0; c2 < 16; ++c2)
                y2[c2] = fma2(p2, gr[c2], y2[c2]);
        }
    }

    // combine the 4 partial accumulators per row
    #pragma unroll
    for (int i = 0; i < 16; ++i) {
        y2[i] = add2(y2[i], __shfl_xor_sync(0xffffffffu, y2[i], 1));
        y2[i] = add2(y2[i], __shfl_xor_sync(0xffffffffu, y2[i], 2));
    }
    run_sum += __shfl_xor_sync(0xffffffffu, run_sum, 1);
    run_sum += __shfl_xor_sync(0xffffffffu, run_sum, 2);

    const float inv = 1.0f / run_sum;
    float y[32];
    #pragma unroll
    for (int i = 0; i < 16; ++i) {
        float lo, hi; upk2(y2[i], lo, hi);
        y[2 * i]     = lo * inv;
        y[2 * i + 1] = hi * inv;
    }

    // epilogue: out[b][c][n] = y . w_out[c] + b_out[c] + x[b][c][n]
    const int n = n0 + r;
    #pragma unroll
    for (int jj = 0; jj < 16; ++jj) {
        const int c = 4 * jj + q;
        float acc = b_out[c];
        #pragma unroll
        for (int ci = 0; ci < 32; ++ci)
            acc = fmaf(woS[c][ci], y[ci], acc);
        const size_t oi = ((size_t)(b * CC + c)) * NN + n;
        out[oi] = acc + x[oi];
    }
}

// ---------------------------------------------------------------------------
extern "C" void kernel_launch(void* const* d_in, const int* in_sizes, int n_in,
                              void* d_out, int out_size)
{
    const float* x  = (const float*)d_in[0];
    const float* wt = (const float*)d_in[1];
    const float* bt = (const float*)d_in[2];
    const float* wp = (const float*)d_in[3];
    const float* bp = (const float*)d_in[4];
    const float* wg = (const float*)d_in[5];
    const float* bg = (const float*)d_in[6];
    const float* wo = (const float*)d_in[7];
    const float* bo = (const float*)d_in[8];
    float* out = (float*)d_out;

    dim3 grid(NN / 64, BB);
    proj_kernel<<<grid, 256>>>(x, wt, bt, wp, bp, wg, bg);
    attn_kernel<<<grid, 256>>>(x, wo, bo, out);
}

// round 2
// speedup vs baseline: 2.8282x; 2.8282x over previous
#include <cuda_runtime.h>
#include <cuda_bf16.h>

// ---------------------------------------------------------------------------
// NonlocalBlock: B=4, C=64, N=9216, Ci=32, M=N/2=4608
// out = x + ( softmax(theta @ phi^T) @ g ) @ w_out^T + b_out
// Round 2: tensor-core (mma.sync tf32) flash-attention. 3xTF32 for scores,
// 1xTF32 for P@g. Proj kernel pre-splits operands into tf32 hi/lo.
// ---------------------------------------------------------------------------

#define BB 4
#define CC 64
#define NN 9216
#define CI 32
#define MM 4608

// scratch (__device__ globals: allocation-free rule)
__device__ float d_th_hi[(size_t)BB * NN * CI];
__device__ float d_th_lo[(size_t)BB * NN * CI];
__device__ float d_ph_hi[(size_t)BB * MM * CI];
__device__ float d_ph_lo[(size_t)BB * MM * CI];
__device__ float d_gv   [(size_t)BB * MM * CI];   // tf32-rounded g

__device__ __forceinline__ float tf32r(float a) {
    unsigned u;
    asm("cvt.rna.tf32.f32 %0, %1;" : "=r"(u) : "f"(a));
    return __uint_as_float(u);
}
__device__ __forceinline__ unsigned tf32b(float a) {
    unsigned u;
    asm("cvt.rna.tf32.f32 %0, %1;" : "=r"(u) : "f"(a));
    return u;
}

// D += A(16x8) * B(8x8), tf32 in / f32 accum
__device__ __forceinline__ void mma8(float* c, const unsigned* a,
                                     unsigned b0, unsigned b1) {
    asm volatile(
        "mma.sync.aligned.m16n8k8.row.col.f32.tf32.tf32.f32 "
        "{%0,%1,%2,%3}, {%4,%5,%6,%7}, {%8,%9}, {%0,%1,%2,%3};"
        : "+f"(c[0]), "+f"(c[1]), "+f"(c[2]), "+f"(c[3])
        : "r"(a[0]), "r"(a[1]), "r"(a[2]), "r"(a[3]), "r"(b0), "r"(b1));
}

// ---------------------------------------------------------------------------
// Kernel 1: projections + maxpool + tf32 hi/lo split.
// grid = (NN/64, BB), 256 threads.
// ---------------------------------------------------------------------------
__global__ __launch_bounds__(256, 2)
void proj_kernel(const float* __restrict__ x,
                 const float* __restrict__ wt, const float* __restrict__ bt,
                 const float* __restrict__ wp, const float* __restrict__ bp,
                 const float* __restrict__ wg, const float* __restrict__ bg)
{
    __shared__ float xs[64][65];
    __shared__ float wts[64][32];
    __shared__ float wps[64][32];
    __shared__ float wgs[64][32];

    const int b  = blockIdx.y;
    const int n0 = blockIdx.x * 64;
    const int tid = threadIdx.x;

    for (int i = tid; i < CI * CC; i += 256) {
        int ci = i >> 6, c = i & 63;
        wts[c][ci] = wt[i];
        wps[c][ci] = wp[i];
        wgs[c][ci] = wg[i];
    }
    for (int i = tid; i < 64 * 64; i += 256) {
        int c = i >> 6, nl = i & 63;
        xs[nl][c] = x[((size_t)(b * CC + c)) * NN + n0 + nl];
    }
    __syncthreads();

    const int ci = tid & 31;
    const int g8 = tid >> 5;
    const float bth = bt[ci], bph = bp[ci], bgg = bg[ci];

    float prev_p = 0.f, prev_g = 0.f;
    #pragma unroll
    for (int i = 0; i < 8; ++i) {
        const int nl = g8 * 8 + i;
        float at = 0.f, ap = 0.f, ag = 0.f;
        #pragma unroll
        for (int c = 0; c < CC; ++c) {
            const float xv = xs[nl][c];
            at = fmaf(xv, wts[c][ci], at);
            ap = fmaf(xv, wps[c][ci], ap);
            ag = fmaf(xv, wgs[c][ci], ag);
        }
        at += bth; ap += bph; ag += bgg;
        {
            const size_t ti = ((size_t)(b * NN + n0 + nl)) * CI + ci;
            float hi = tf32r(at);
            d_th_hi[ti] = hi;
            d_th_lo[ti] = tf32r(at - hi);
        }
        if (i & 1) {
            const int m = (n0 + nl) >> 1;
            const size_t mi = ((size_t)(b * MM + m)) * CI + ci;
            float pv = fmaxf(prev_p, ap);
            float hv = tf32r(pv);
            d_ph_hi[mi] = hv;
            d_ph_lo[mi] = tf32r(pv - hv);
            d_gv[mi] = tf32r(fmaxf(prev_g, ag));
        } else {
            prev_p = ap; prev_g = ag;
        }
    }
}

// ---------------------------------------------------------------------------
// Kernel 2: tensor-core flash attention + out-proj + residual.
// grid = (NN/64, BB), 128 threads (4 warps x 16 query rows).
// ---------------------------------------------------------------------------
__global__ __launch_bounds__(128, 4)
void attn_kernel(const float* __restrict__ x,
                 const float* __restrict__ w_out,
                 const float* __restrict__ b_out,
                 float* __restrict__ out)
{
    __shared__ float phiH[64][36];   // [key][ci], bank = 4g+t conflict-free
    __shared__ float phiL[64][36];
    __shared__ float gT[32][68];     // [ci][key] transposed
    __shared__ float woS[64][33];    // [c][ci]

    const int b    = blockIdx.y;
    const int n0b  = blockIdx.x * 64;
    const int tid  = threadIdx.x;
    const int warp = tid >> 5;
    const int lane = tid & 31;
    const int grp  = lane >> 2;      // groupID (row within 8)
    const int t    = lane & 3;       // thread-in-group

    for (int i = tid; i < CC * CI; i += 128) {
        int c = i >> 5, ci = i & 31;
        woS[c][ci] = w_out[i];
    }

    // ---- theta A fragments (hi/lo), loaded once -------------------------
    const int row0 = warp * 16 + grp;      // local rows row0, row0+8
    unsigned aH[4][4], aL[4][4];
    {
        const unsigned* thH = (const unsigned*)d_th_hi + ((size_t)(b * NN + n0b)) * CI;
        const unsigned* thL = (const unsigned*)d_th_lo + ((size_t)(b * NN + n0b)) * CI;
        #pragma unroll
        for (int ks = 0; ks < 4; ++ks) {
            const int c0 = ks * 8 + t;
            aH[ks][0] = thH[(size_t)row0 * CI + c0];
            aH[ks][1] = thH[(size_t)(row0 + 8) * CI + c0];
            aH[ks][2] = thH[(size_t)row0 * CI + c0 + 4];
            aH[ks][3] = thH[(size_t)(row0 + 8) * CI + c0 + 4];
            aL[ks][0] = thL[(size_t)row0 * CI + c0];
            aL[ks][1] = thL[(size_t)(row0 + 8) * CI + c0];
            aL[ks][2] = thL[(size_t)row0 * CI + c0 + 4];
            aL[ks][3] = thL[(size_t)(row0 + 8) * CI + c0 + 4];
        }
    }

    float y[4][4];                    // 4 ch n-tiles, C-frag layout
    #pragma unroll
    for (int i = 0; i < 4; ++i)
        #pragma unroll
        for (int j = 0; j < 4; ++j) y[i][j] = 0.f;
    float rm0 = -1e30f, rm1 = -1e30f, rs0 = 0.f, rs1 = 0.f;

    const float* phB = d_ph_hi + ((size_t)b * MM) * CI;
    const float* plB = d_ph_lo + ((size_t)b * MM) * CI;
    const float* gB  = d_gv    + ((size_t)b * MM) * CI;

    for (int mt = 0; mt < MM / 64; ++mt) {
        __syncthreads();
        // stage phi hi/lo [key][36]
        {
            const float4* p4 = (const float4*)(phB + (size_t)mt * 64 * CI);
            const float4* l4 = (const float4*)(plB + (size_t)mt * 64 * CI);
            #pragma unroll
            for (int it = 0; it < 4; ++it) {
                int idx = tid + it * 128;          // 0..511
                int key = idx >> 3, c4 = (idx & 7) << 2;
                *(float4*)&phiH[key][c4] = p4[idx];
                *(float4*)&phiL[key][c4] = l4[idx];
            }
            // g transposed: lane -> key, iter -> ci group (conflict-free STS)
            const float* gt = gB + (size_t)mt * 64 * CI;
            #pragma unroll
            for (int it = 0; it < 4; ++it) {
                int idx = tid + it * 128;          // 0..511
                int key = idx & 63, c4 = (idx >> 6) << 2;
                float4 v = *(const float4*)(gt + (size_t)key * CI + c4);
                gT[c4 + 0][key] = v.x;
                gT[c4 + 1][key] = v.y;
                gT[c4 + 2][key] = v.z;
                gT[c4 + 3][key] = v.w;
            }
        }
        __syncthreads();

        // ---- S = theta . phi^T   (3xTF32) -------------------------------
        float s[8][4];
        #pragma unroll
        for (int nt = 0; nt < 8; ++nt) {
            s[nt][0] = s[nt][1] = s[nt][2] = s[nt][3] = 0.f;
            const int key = nt * 8 + grp;
            #pragma unroll
            for (int ks = 0; ks < 4; ++ks) {
                const int c0 = ks * 8 + t;
                unsigned bh0 = __float_as_uint(phiH[key][c0]);
                unsigned bh1 = __float_as_uint(phiH[key][c0 + 4]);
                unsigned bl0 = __float_as_uint(phiL[key][c0]);
                unsigned bl1 = __float_as_uint(phiL[key][c0 + 4]);
                mma8(s[nt], aH[ks], bh0, bh1);
                mma8(s[nt], aH[ks], bl0, bl1);
                mma8(s[nt], aL[ks], bh0, bh1);
            }
        }

        // ---- online softmax ---------------------------------------------
        float m0 = s[0][0], m1 = s[0][2];
        #pragma unroll
        for (int nt = 0; nt < 8; ++nt) {
            m0 = fmaxf(m0, fmaxf(s[nt][0], s[nt][1]));
            m1 = fmaxf(m1, fmaxf(s[nt][2], s[nt][3]));
        }
        m0 = fmaxf(m0, __shfl_xor_sync(0xffffffffu, m0, 1));
        m0 = fmaxf(m0, __shfl_xor_sync(0xffffffffu, m0, 2));
        m1 = fmaxf(m1, __shfl_xor_sync(0xffffffffu, m1, 1));
        m1 = fmaxf(m1, __shfl_xor_sync(0xffffffffu, m1, 2));

        const float nm0 = fmaxf(rm0, m0);
        const float nm1 = fmaxf(rm1, m1);
        const float sc0 = __expf(rm0 - nm0);
        const float sc1 = __expf(rm1 - nm1);
        rm0 = nm0; rm1 = nm1;
        rs0 *= sc0; rs1 *= sc1;
        #pragma unroll
        for (int nc = 0; nc < 4; ++nc) {
            y[nc][0] *= sc0; y[nc][1] *= sc0;
            y[nc][2] *= sc1; y[nc][3] *= sc1;
        }

        const int srcA = (lane & ~3) | (t >> 1);
        const int srcB = srcA + 2;

        // ---- P = exp(S - m);  y += P @ g  (1xTF32) ----------------------
        #pragma unroll
        for (int nt = 0; nt < 8; ++nt) {
            float p0 = __expf(s[nt][0] - nm0);
            float p1 = __expf(s[nt][1] - nm0);
            float p2 = __expf(s[nt][2] - nm1);
            float p3 = __expf(s[nt][3] - nm1);
            rs0 += p0 + p1;
            rs1 += p2 + p3;
            unsigned u0 = tf32b(p0), u1 = tf32b(p1);
            unsigned u2 = tf32b(p2), u3 = tf32b(p3);

            // C-frag (cols 2t,2t+1) -> A-frag (cols t, t+4)
            unsigned pa[4];
            unsigned e, o;
            e = __shfl_sync(0xffffffffu, u0, srcA);
            o = __shfl_sync(0xffffffffu, u1, srcA);
            pa[0] = (t & 1) ? o : e;
            e = __shfl_sync(0xffffffffu, u2, srcA);
            o = __shfl_sync(0xffffffffu, u3, srcA);
            pa[1] = (t & 1) ? o : e;
            e = __shfl_sync(0xffffffffu, u0, srcB);
            o = __shfl_sync(0xffffffffu, u1, srcB);
            pa[2] = (t & 1) ? o : e;
            e = __shfl_sync(0xffffffffu, u2, srcB);
            o = __shfl_sync(0xffffffffu, u3, srcB);
            pa[3] = (t & 1) ? o : e;

            const int key0 = nt * 8 + t;
            #pragma unroll
            for (int nc = 0; nc < 4; ++nc) {
                const int ch = nc * 8 + grp;
                unsigned b0 = __float_as_uint(gT[ch][key0]);
                unsigned b1 = __float_as_uint(gT[ch][key0 + 4]);
                mma8(y[nc], pa, b0, b1);
            }
        }
    }

    // combine partial sums across the 4 lanes of each row group
    rs0 += __shfl_xor_sync(0xffffffffu, rs0, 1);
    rs0 += __shfl_xor_sync(0xffffffffu, rs0, 2);
    rs1 += __shfl_xor_sync(0xffffffffu, rs1, 1);
    rs1 += __shfl_xor_sync(0xffffffffu, rs1, 2);
    const float inv0 = 1.0f / rs0;
    const float inv1 = 1.0f / rs1;

    __syncthreads();                       // done reading phiH -> reuse as ySm
    #pragma unroll
    for (int nc = 0; nc < 4; ++nc) {
        phiH[row0][nc * 8 + 2 * t]         = y[nc][0] * inv0;
        phiH[row0][nc * 8 + 2 * t + 1]     = y[nc][1] * inv0;
        phiH[row0 + 8][nc * 8 + 2 * t]     = y[nc][2] * inv1;
        phiH[row0 + 8][nc * 8 + 2 * t + 1] = y[nc][3] * inv1;
    }
    __syncthreads();

    // epilogue: out[b][c][n] = y . w_out[c] + b_out[c] + x[b][c][n]
    {
        const int row  = tid >> 1;          // 0..63
        const int half = tid & 1;           // c in [32h, 32h+32)
        float yv[32];
        #pragma unroll
        for (int i = 0; i < 32; ++i) yv[i] = phiH[row][i];
        const int n = n0b + row;
        #pragma unroll
        for (int j = 0; j < 32; ++j) {
            const int c = half * 32 + j;
            float acc = b_out[c];
            #pragma unroll
            for (int ci = 0; ci < 32; ++ci)
                acc = fmaf(woS[c][ci], yv[ci], acc);
            const size_t oi = ((size_t)(b * CC + c)) * NN + n;
            out[oi] = acc + x[oi];
        }
    }
}

// ---------------------------------------------------------------------------
extern "C" void kernel_launch(void* const* d_in, const int* in_sizes, int n_in,
                              void* d_out, int out_size)
{
    const float* x  = (const float*)d_in[0];
    const float* wt = (const float*)d_in[1];
    const float* bt = (const float*)d_in[2];
    const float* wp = (const float*)d_in[3];
    const float* bp = (const float*)d_in[4];
    const float* wg = (const float*)d_in[5];
    const float* bg = (const float*)d_in[6];
    const float* wo = (const float*)d_in[7];
    const float* bo = (const float*)d_in[8];
    float* out = (float*)d_out;

    dim3 grid(NN / 64, BB);
    proj_kernel<<<grid, 256>>>(x, wt, bt, wp, bp, wg, bg);
    attn_kernel<<<grid, 128>>>(x, wo, bo, out);
}

// round 3
// speedup vs baseline: 4.4250x; 1.5646x over previous
#include <cuda_runtime.h>
#include <cuda_bf16.h>

// ---------------------------------------------------------------------------
// NonlocalBlock: B=4, C=64, N=9216, Ci=32, M=4608
// Round 3: S via split-bf16 mma.m16n8k16 + ldmatrix; P@g via tf32 m16n8k8;
// cp.async double-buffered staging.
// ---------------------------------------------------------------------------

#define BB 4
#define CC 64
#define NN 9216
#define CI 32
#define MM 4608
#define TILES (MM / 64)

// scratch (__device__ globals: allocation-free rule)
__device__ __nv_bfloat16 d_thH[(size_t)BB * NN * CI];
__device__ __nv_bfloat16 d_thL[(size_t)BB * NN * CI];
__device__ __nv_bfloat16 d_phH[(size_t)BB * MM * CI];
__device__ __nv_bfloat16 d_phL[(size_t)BB * MM * CI];
__device__ float d_gT[(size_t)BB * CI * MM];        // transposed, tf32-rounded

__device__ __forceinline__ float tf32r(float a) {
    unsigned u; asm("cvt.rna.tf32.f32 %0, %1;" : "=r"(u) : "f"(a));
    return __uint_as_float(u);
}
__device__ __forceinline__ unsigned tf32b(float a) {
    unsigned u; asm("cvt.rna.tf32.f32 %0, %1;" : "=r"(u) : "f"(a));
    return u;
}

// D += A(16x8) * B(8x8), tf32
__device__ __forceinline__ void mma8(float* c, const unsigned* a,
                                     unsigned b0, unsigned b1) {
    asm volatile(
        "mma.sync.aligned.m16n8k8.row.col.f32.tf32.tf32.f32 "
        "{%0,%1,%2,%3}, {%4,%5,%6,%7}, {%8,%9}, {%0,%1,%2,%3};"
        : "+f"(c[0]), "+f"(c[1]), "+f"(c[2]), "+f"(c[3])
        : "r"(a[0]), "r"(a[1]), "r"(a[2]), "r"(a[3]), "r"(b0), "r"(b1));
}
// D += A(16x16) * B(16x8), bf16
__device__ __forceinline__ void mma16(float* c, const unsigned* a,
                                      unsigned b0, unsigned b1) {
    asm volatile(
        "mma.sync.aligned.m16n8k16.row.col.f32.bf16.bf16.f32 "
        "{%0,%1,%2,%3}, {%4,%5,%6,%7}, {%8,%9}, {%0,%1,%2,%3};"
        : "+f"(c[0]), "+f"(c[1]), "+f"(c[2]), "+f"(c[3])
        : "r"(a[0]), "r"(a[1]), "r"(a[2]), "r"(a[3]), "r"(b0), "r"(b1));
}
__device__ __forceinline__ uint4 ldsm4(unsigned a) {
    uint4 r;
    asm volatile("ldmatrix.sync.aligned.m8n8.x4.shared.b16 {%0,%1,%2,%3}, [%4];"
                 : "=r"(r.x), "=r"(r.y), "=r"(r.z), "=r"(r.w) : "r"(a));
    return r;
}
__device__ __forceinline__ void cpa16(unsigned s, const void* g) {
    asm volatile("cp.async.ca.shared.global [%0], [%1], 16;" :: "r"(s), "l"(g));
}
__device__ __forceinline__ void cpcommit() { asm volatile("cp.async.commit_group;"); }
template <int N> __device__ __forceinline__ void cpwait() {
    asm volatile("cp.async.wait_group %0;" :: "n"(N));
}

// ---------------------------------------------------------------------------
// Kernel 1: projections + maxpool + bf16 hi/lo split (+ transposed g).
// grid = (NN/64, BB), 256 threads.
// ---------------------------------------------------------------------------
__global__ __launch_bounds__(256, 2)
void proj_kernel(const float* __restrict__ x,
                 const float* __restrict__ wt, const float* __restrict__ bt,
                 const float* __restrict__ wp, const float* __restrict__ bp,
                 const float* __restrict__ wg, const float* __restrict__ bg)
{
    __shared__ float xs[64][65];
    __shared__ float wts[64][32];
    __shared__ float wps[64][32];
    __shared__ float wgs[64][32];

    const int b  = blockIdx.y;
    const int n0 = blockIdx.x * 64;
    const int tid = threadIdx.x;

    for (int i = tid; i < CI * CC; i += 256) {
        int ci = i >> 6, c = i & 63;
        wts[c][ci] = wt[i];
        wps[c][ci] = wp[i];
        wgs[c][ci] = wg[i];
    }
    for (int i = tid; i < 64 * 64; i += 256) {
        int c = i >> 6, nl = i & 63;
        xs[nl][c] = x[((size_t)(b * CC + c)) * NN + n0 + nl];
    }
    __syncthreads();

    const int ci = tid & 31;
    const int g8 = tid >> 5;
    const float bth = bt[ci], bph = bp[ci], bgg = bg[ci];

    float prev_p = 0.f, prev_g = 0.f;
    #pragma unroll
    for (int i = 0; i < 8; ++i) {
        const int nl = g8 * 8 + i;
        float at = 0.f, ap = 0.f, ag = 0.f;
        #pragma unroll
        for (int c = 0; c < CC; ++c) {
            const float xv = xs[nl][c];
            at = fmaf(xv, wts[c][ci], at);
            ap = fmaf(xv, wps[c][ci], ap);
            ag = fmaf(xv, wgs[c][ci], ag);
        }
        at += bth; ap += bph; ag += bgg;
        {
            const size_t ti = ((size_t)(b * NN + n0 + nl)) * CI + ci;
            __nv_bfloat16 h = __float2bfloat16_rn(at);
            d_thH[ti] = h;
            d_thL[ti] = __float2bfloat16_rn(at - __bfloat162float(h));
        }
        if (i & 1) {
            const int m = (n0 + nl) >> 1;
            const size_t mi = ((size_t)(b * MM + m)) * CI + ci;
            float pv = fmaxf(prev_p, ap);
            __nv_bfloat16 h = __float2bfloat16_rn(pv);
            d_phH[mi] = h;
            d_phL[mi] = __float2bfloat16_rn(pv - __bfloat162float(h));
            d_gT[((size_t)(b * CI + ci)) * MM + m] = tf32r(fmaxf(prev_g, ag));
        } else {
            prev_p = ap; prev_g = ag;
        }
    }
}

// ---------------------------------------------------------------------------
// smem byte offsets for attn kernel
// ---------------------------------------------------------------------------
#define PH0o 0           // 64 keys x 40 bf16 (80 B rows) = 5120
#define PL0o 5120
#define PH1o 10240
#define PL1o 15360
#define GT0o 20480       // 32 ci x 68 floats (272 B rows) = 8704
#define GT1o 29184
#define WOo  37888       // 64 x 33 floats = 8448
#define SMSZ 46336

// ---------------------------------------------------------------------------
// Kernel 2: flash attention + out-proj + residual.
// grid = (NN/64, BB), 128 threads (4 warps x 16 query rows).
// ---------------------------------------------------------------------------
__global__ __launch_bounds__(128, 4)
void attn_kernel(const float* __restrict__ x,
                 const float* __restrict__ w_out,
                 const float* __restrict__ b_out,
                 float* __restrict__ out)
{
    __shared__ __align__(16) unsigned char SM[SMSZ];
    const unsigned shb = (unsigned)__cvta_generic_to_shared(SM);

    const int b    = blockIdx.y;
    const int n0b  = blockIdx.x * 64;
    const int tid  = threadIdx.x;
    const int warp = tid >> 5;
    const int lane = tid & 31;
    const int grp  = lane >> 2;
    const int t    = lane & 3;

    float* woS = (float*)(SM + WOo);
    for (int i = tid; i < CC * CI; i += 128) {
        int c = i >> 5, ci = i & 31;
        woS[c * 33 + ci] = w_out[i];
    }

    // ---- theta A fragments (bf16 hi/lo), 2 k16 chunks -------------------
    const int row0 = warp * 16 + grp;
    unsigned aH[2][4], aL[2][4];
    {
        const __nv_bfloat16* thH = d_thH + ((size_t)(b * NN + n0b)) * CI;
        const __nv_bfloat16* thL = d_thL + ((size_t)(b * NN + n0b)) * CI;
        #pragma unroll
        for (int ch = 0; ch < 2; ++ch) {
            const int c0 = ch * 16 + 2 * t;
            aH[ch][0] = *(const unsigned*)(thH + (size_t)row0 * CI + c0);
            aH[ch][1] = *(const unsigned*)(thH + (size_t)(row0 + 8) * CI + c0);
            aH[ch][2] = *(const unsigned*)(thH + (size_t)row0 * CI + c0 + 8);
            aH[ch][3] = *(const unsigned*)(thH + (size_t)(row0 + 8) * CI + c0 + 8);
            aL[ch][0] = *(const unsigned*)(thL + (size_t)row0 * CI + c0);
            aL[ch][1] = *(const unsigned*)(thL + (size_t)(row0 + 8) * CI + c0);
            aL[ch][2] = *(const unsigned*)(thL + (size_t)row0 * CI + c0 + 8);
            aL[ch][3] = *(const unsigned*)(thL + (size_t)(row0 + 8) * CI + c0 + 8);
        }
    }

    float y[4][4];
    #pragma unroll
    for (int i = 0; i < 4; ++i)
        #pragma unroll
        for (int j = 0; j < 4; ++j) y[i][j] = 0.f;
    float rm0 = -1e30f, rm1 = -1e30f, rs0 = 0.f, rs1 = 0.f;

    const char* gphH = (const char*)(d_phH + ((size_t)b * MM) * CI);
    const char* gphL = (const char*)(d_phL + ((size_t)b * MM) * CI);
    const char* ggT  = (const char*)(d_gT + (size_t)b * CI * MM);

    // tile copy: phi h/l (256 chunks each... 256 total each of 16B? 64*64B=4KB
    // = 256 x 16B), g 512 x 16B
    auto copy_tile = [&](int mt, int buf) {
        const unsigned phO = buf ? PH1o : PH0o;
        const unsigned plO = buf ? PL1o : PL0o;
        const unsigned gtO = buf ? GT1o : GT0o;
        const char* ph = gphH + (size_t)mt * 64 * CI * 2;
        const char* pl = gphL + (size_t)mt * 64 * CI * 2;
        #pragma unroll
        for (int it = 0; it < 2; ++it) {
            int idx = tid + it * 128;          // 0..255
            int key = idx >> 2, c = idx & 3;
            cpa16(shb + phO + key * 80 + c * 16, ph + idx * 16);
            cpa16(shb + plO + key * 80 + c * 16, pl + idx * 16);
        }
        const char* gg = ggT + (size_t)mt * 64 * 4;
        #pragma unroll
        for (int it = 0; it < 4; ++it) {
            int idx = tid + it * 128;          // 0..511
            int ci = idx >> 4, c = idx & 15;
            cpa16(shb + gtO + ci * 272 + c * 16, gg + (size_t)ci * MM * 4 + c * 16);
        }
    };

    copy_tile(0, 0);
    cpcommit();

    const unsigned lmBase = (lane & 7) * 80 + (lane >> 3) * 16;
    const int srcA = (lane & ~3) | (t >> 1);
    const int srcB = srcA + 2;

    for (int mt = 0; mt < TILES; ++mt) {
        const int cur = mt & 1;
        if (mt + 1 < TILES) { copy_tile(mt + 1, cur ^ 1); cpcommit(); cpwait<1>(); }
        else                { cpwait<0>(); }
        __syncthreads();

        const unsigned phA = shb + (cur ? PH1o : PL0o - 5120) + lmBase; // PH0o=0
        const unsigned plA = phA + 5120;
        const float* gTp = (const float*)(SM + (cur ? GT1o : GT0o));

        // ---- S = theta . phi^T  (split-bf16, 6 mmas / key-group) --------
        float s[8][4];
        #pragma unroll
        for (int nt = 0; nt < 8; ++nt) {
            s[nt][0] = s[nt][1] = s[nt][2] = s[nt][3] = 0.f;
            uint4 bh = ldsm4(phA + nt * 640);
            uint4 bl = ldsm4(plA + nt * 640);
            mma16(s[nt], aH[0], bh.x, bh.y);
            mma16(s[nt], aH[1], bh.z, bh.w);
            mma16(s[nt], aL[0], bh.x, bh.y);
            mma16(s[nt], aL[1], bh.z, bh.w);
            mma16(s[nt], aH[0], bl.x, bl.y);
            mma16(s[nt], aH[1], bl.z, bl.w);
        }

        // ---- online softmax ---------------------------------------------
        float m0 = s[0][0], m1 = s[0][2];
        #pragma unroll
        for (int nt = 0; nt < 8; ++nt) {
            m0 = fmaxf(m0, fmaxf(s[nt][0], s[nt][1]));
            m1 = fmaxf(m1, fmaxf(s[nt][2], s[nt][3]));
        }
        m0 = fmaxf(m0, __shfl_xor_sync(0xffffffffu, m0, 1));
        m0 = fmaxf(m0, __shfl_xor_sync(0xffffffffu, m0, 2));
        m1 = fmaxf(m1, __shfl_xor_sync(0xffffffffu, m1, 1));
        m1 = fmaxf(m1, __shfl_xor_sync(0xffffffffu, m1, 2));

        const float nm0 = fmaxf(rm0, m0);
        const float nm1 = fmaxf(rm1, m1);
        const float sc0 = __expf(rm0 - nm0);
        const float sc1 = __expf(rm1 - nm1);
        rm0 = nm0; rm1 = nm1;
        rs0 *= sc0; rs1 *= sc1;
        #pragma unroll
        for (int nc = 0; nc < 4; ++nc) {
            y[nc][0] *= sc0; y[nc][1] *= sc0;
            y[nc][2] *= sc1; y[nc][3] *= sc1;
        }

        // ---- P = exp(S - m);  y += P @ g  (tf32) ------------------------
        #pragma unroll
        for (int nt = 0; nt < 8; ++nt) {
            float p0 = __expf(s[nt][0] - nm0);
            float p1 = __expf(s[nt][1] - nm0);
            float p2 = __expf(s[nt][2] - nm1);
            float p3 = __expf(s[nt][3] - nm1);
            rs0 += p0 + p1;
            rs1 += p2 + p3;
            unsigned u0 = tf32b(p0), u1 = tf32b(p1);
            unsigned u2 = tf32b(p2), u3 = tf32b(p3);

            unsigned pa[4];
            unsigned e, o;
            e = __shfl_sync(0xffffffffu, u0, srcA);
            o = __shfl_sync(0xffffffffu, u1, srcA);
            pa[0] = (t & 1) ? o : e;
            e = __shfl_sync(0xffffffffu, u2, srcA);
            o = __shfl_sync(0xffffffffu, u3, srcA);
            pa[1] = (t & 1) ? o : e;
            e = __shfl_sync(0xffffffffu, u0, srcB);
            o = __shfl_sync(0xffffffffu, u1, srcB);
            pa[2] = (t & 1) ? o : e;
            e = __shfl_sync(0xffffffffu, u2, srcB);
            o = __shfl_sync(0xffffffffu, u3, srcB);
            pa[3] = (t & 1) ? o : e;

            const int key0 = nt * 8 + t;
            #pragma unroll
            for (int nc = 0; nc < 4; ++nc) {
                const int ch = nc * 8 + grp;
                unsigned b0 = __float_as_uint(gTp[ch * 68 + key0]);
                unsigned b1 = __float_as_uint(gTp[ch * 68 + key0 + 4]);
                mma8(y[nc], pa, b0, b1);
            }
        }
        __syncthreads();
    }

    // combine partial sums across the 4 lanes of each row group
    rs0 += __shfl_xor_sync(0xffffffffu, rs0, 1);
    rs0 += __shfl_xor_sync(0xffffffffu, rs0, 2);
    rs1 += __shfl_xor_sync(0xffffffffu, rs1, 1);
    rs1 += __shfl_xor_sync(0xffffffffu, rs1, 2);
    const float inv0 = 1.0f / rs0;
    const float inv1 = 1.0f / rs1;

    float* ySm = (float*)(SM + GT0o);      // reuse (>= 64*33*4 bytes)
    #pragma unroll
    for (int nc = 0; nc < 4; ++nc) {
        ySm[row0 * 33 + nc * 8 + 2 * t]           = y[nc][0] * inv0;
        ySm[row0 * 33 + nc * 8 + 2 * t + 1]       = y[nc][1] * inv0;
        ySm[(row0 + 8) * 33 + nc * 8 + 2 * t]     = y[nc][2] * inv1;
        ySm[(row0 + 8) * 33 + nc * 8 + 2 * t + 1] = y[nc][3] * inv1;
    }
    __syncthreads();

    // epilogue: out[b][c][n] = y . w_out[c] + b_out[c] + x[b][c][n]
    {
        const int row  = tid >> 1;
        const int half = tid & 1;
        float yv[32];
        #pragma unroll
        for (int i = 0; i < 32; ++i) yv[i] = ySm[row * 33 + i];
        const int n = n0b + row;
        #pragma unroll
        for (int j = 0; j < 32; ++j) {
            const int c = half * 32 + j;
            float acc = b_out[c];
            #pragma unroll
            for (int ci = 0; ci < 32; ++ci)
                acc = fmaf(woS[c * 33 + ci], yv[ci], acc);
            const size_t oi = ((size_t)(b * CC + c)) * NN + n;
            out[oi] = acc + x[oi];
        }
    }
}

// ---------------------------------------------------------------------------
extern "C" void kernel_launch(void* const* d_in, const int* in_sizes, int n_in,
                              void* d_out, int out_size)
{
    const float* x  = (const float*)d_in[0];
    const float* wt = (const float*)d_in[1];
    const float* bt = (const float*)d_in[2];
    const float* wp = (const float*)d_in[3];
    const float* bp = (const float*)d_in[4];
    const float* wg = (const float*)d_in[5];
    const float* bg = (const float*)d_in[6];
    const float* wo = (const float*)d_in[7];
    const float* bo = (const float*)d_in[8];
    float* out = (float*)d_out;

    dim3 grid(NN / 64, BB);
    proj_kernel<<<grid, 256>>>(x, wt, bt, wp, bp, wg, bg);
    attn_kernel<<<grid, 128>>>(x, wo, bo, out);
}

// round 4
// speedup vs baseline: 5.3808x; 1.2160x over previous
#include <cuda_runtime.h>
#include <cuda_bf16.h>

// ---------------------------------------------------------------------------
// NonlocalBlock: B=4, C=64, N=9216, Ci=32, M=4608
// Round 4: shuffle-free P@g via bf16 C-frag==A-frag identity + ldmatrix g.
// S: split-bf16 (theta pre-scaled by log2e). P@g: pH*gH + pH*gL + pL*gH.
// ---------------------------------------------------------------------------

#define BB 4
#define CC 64
#define NN 9216
#define CI 32
#define MM 4608
#define TILES (MM / 64)
#define LOG2E 1.4426950408889634f

// scratch (__device__ globals: allocation-free rule)
__device__ __nv_bfloat16 d_thH[(size_t)BB * NN * CI];   // theta*log2e hi
__device__ __nv_bfloat16 d_thL[(size_t)BB * NN * CI];   // theta*log2e lo
__device__ __nv_bfloat16 d_phH[(size_t)BB * MM * CI];
__device__ __nv_bfloat16 d_phL[(size_t)BB * MM * CI];
__device__ __nv_bfloat16 d_gTH[(size_t)BB * CI * MM];   // g transposed, hi
__device__ __nv_bfloat16 d_gTL[(size_t)BB * CI * MM];   // g transposed, lo

// D += A(16x16) * B(16x8), bf16
__device__ __forceinline__ void mma16(float* c, const unsigned* a,
                                      unsigned b0, unsigned b1) {
    asm volatile(
        "mma.sync.aligned.m16n8k16.row.col.f32.bf16.bf16.f32 "
        "{%0,%1,%2,%3}, {%4,%5,%6,%7}, {%8,%9}, {%0,%1,%2,%3};"
        : "+f"(c[0]), "+f"(c[1]), "+f"(c[2]), "+f"(c[3])
        : "r"(a[0]), "r"(a[1]), "r"(a[2]), "r"(a[3]), "r"(b0), "r"(b1));
}
__device__ __forceinline__ uint4 ldsm4(unsigned a) {
    uint4 r;
    asm volatile("ldmatrix.sync.aligned.m8n8.x4.shared.b16 {%0,%1,%2,%3}, [%4];"
                 : "=r"(r.x), "=r"(r.y), "=r"(r.z), "=r"(r.w) : "r"(a));
    return r;
}
__device__ __forceinline__ void cpa16(unsigned s, const void* g) {
    asm volatile("cp.async.ca.shared.global [%0], [%1], 16;" :: "r"(s), "l"(g));
}
__device__ __forceinline__ void cpcommit() { asm volatile("cp.async.commit_group;"); }
template <int N> __device__ __forceinline__ void cpwait() {
    asm volatile("cp.async.wait_group %0;" :: "n"(N));
}
// pack top-16-bits of two fp32 -> bf16x2 {lo=a_hi16, hi=b_hi16}
__device__ __forceinline__ unsigned prmt7632(unsigned a, unsigned b) {
    unsigned d; asm("prmt.b32 %0, %1, %2, 0x7632;" : "=r"(d) : "r"(a), "r"(b));
    return d;
}
// round-to-nearest pack {lo=bf16(lo), hi=bf16(hi)}
__device__ __forceinline__ unsigned pkbf2(float lo, float hi) {
    unsigned d; asm("cvt.rn.bf16x2.f32 %0, %1, %2;" : "=r"(d) : "f"(hi), "f"(lo));
    return d;
}

// ---------------------------------------------------------------------------
// Kernel 1: projections + maxpool + bf16 hi/lo split (theta scaled by log2e).
// grid = (NN/64, BB), 256 threads (8 warps x 8 positions; lane = ci).
// ---------------------------------------------------------------------------
__global__ __launch_bounds__(256, 2)
void proj_kernel(const float* __restrict__ x,
                 const float* __restrict__ wt, const float* __restrict__ bt,
                 const float* __restrict__ wp, const float* __restrict__ bp,
                 const float* __restrict__ wg, const float* __restrict__ bg)
{
    __shared__ float xs[64][68];          // 16B-aligned rows
    __shared__ float wts[64][32];
    __shared__ float wps[64][32];
    __shared__ float wgs[64][32];

    const int b  = blockIdx.y;
    const int n0 = blockIdx.x * 64;
    const int tid = threadIdx.x;

    for (int i = tid; i < CI * CC; i += 256) {
        int ci = i >> 6, c = i & 63;
        wts[c][ci] = wt[i];
        wps[c][ci] = wp[i];
        wgs[c][ci] = wg[i];
    }
    for (int i = tid; i < 64 * 64; i += 256) {
        int c = i >> 6, nl = i & 63;
        xs[nl][c] = x[((size_t)(b * CC + c)) * NN + n0 + nl];
    }
    __syncthreads();

    const int ci = tid & 31;
    const int g8 = tid >> 5;
    float at[8], ap[8], ag[8];
    #pragma unroll
    for (int i = 0; i < 8; ++i) { at[i] = 0.f; ap[i] = 0.f; ag[i] = 0.f; }

    // chunked: 8 channels' weights in regs, x via vectorized broadcast loads
    #pragma unroll
    for (int cb = 0; cb < 64; cb += 8) {
        float wtr[8], wpr[8], wgr[8];
        #pragma unroll
        for (int k = 0; k < 8; ++k) {
            wtr[k] = wts[cb + k][ci];
            wpr[k] = wps[cb + k][ci];
            wgr[k] = wgs[cb + k][ci];
        }
        #pragma unroll
        for (int i = 0; i < 8; ++i) {
            const int nl = g8 * 8 + i;
            float4 v0 = *(const float4*)&xs[nl][cb];
            float4 v1 = *(const float4*)&xs[nl][cb + 4];
            at[i] = fmaf(v0.x, wtr[0], at[i]); ap[i] = fmaf(v0.x, wpr[0], ap[i]); ag[i] = fmaf(v0.x, wgr[0], ag[i]);
            at[i] = fmaf(v0.y, wtr[1], at[i]); ap[i] = fmaf(v0.y, wpr[1], ap[i]); ag[i] = fmaf(v0.y, wgr[1], ag[i]);
            at[i] = fmaf(v0.z, wtr[2], at[i]); ap[i] = fmaf(v0.z, wpr[2], ap[i]); ag[i] = fmaf(v0.z, wgr[2], ag[i]);
            at[i] = fmaf(v0.w, wtr[3], at[i]); ap[i] = fmaf(v0.w, wpr[3], ap[i]); ag[i] = fmaf(v0.w, wgr[3], ag[i]);
            at[i] = fmaf(v1.x, wtr[4], at[i]); ap[i] = fmaf(v1.x, wpr[4], ap[i]); ag[i] = fmaf(v1.x, wgr[4], ag[i]);
            at[i] = fmaf(v1.y, wtr[5], at[i]); ap[i] = fmaf(v1.y, wpr[5], ap[i]); ag[i] = fmaf(v1.y, wgr[5], ag[i]);
            at[i] = fmaf(v1.z, wtr[6], at[i]); ap[i] = fmaf(v1.z, wpr[6], ap[i]); ag[i] = fmaf(v1.z, wgr[6], ag[i]);
            at[i] = fmaf(v1.w, wtr[7], at[i]); ap[i] = fmaf(v1.w, wpr[7], ap[i]); ag[i] = fmaf(v1.w, wgr[7], ag[i]);
        }
    }

    const float bth = bt[ci], bph = bp[ci], bgg = bg[ci];
    float prev_p = 0.f, prev_g = 0.f;
    #pragma unroll
    for (int i = 0; i < 8; ++i) {
        const int nl = g8 * 8 + i;
        const float tv = (at[i] + bth) * LOG2E;     // fold log2e for exp2
        const float pv0 = ap[i] + bph;
        const float gv0 = ag[i] + bgg;
        {
            const size_t ti = ((size_t)(b * NN + n0 + nl)) * CI + ci;
            __nv_bfloat16 h = __float2bfloat16_rn(tv);
            d_thH[ti] = h;
            d_thL[ti] = __float2bfloat16_rn(tv - __bfloat162float(h));
        }
        if (i & 1) {
            const int m = (n0 + nl) >> 1;
            const size_t mi = ((size_t)(b * MM + m)) * CI + ci;
            float pv = fmaxf(prev_p, pv0);
            __nv_bfloat16 h = __float2bfloat16_rn(pv);
            d_phH[mi] = h;
            d_phL[mi] = __float2bfloat16_rn(pv - __bfloat162float(h));
            float gv = fmaxf(prev_g, gv0);
            __nv_bfloat16 gh = __float2bfloat16_rn(gv);
            const size_t gi = ((size_t)(b * CI + ci)) * MM + m;
            d_gTH[gi] = gh;
            d_gTL[gi] = __float2bfloat16_rn(gv - __bfloat162float(gh));
        } else {
            prev_p = pv0; prev_g = gv0;
        }
    }
}

// ---------------------------------------------------------------------------
// smem byte offsets (static shared < 48KB)
// ---------------------------------------------------------------------------
#define PH0o 0u           // phi hi buf0: 64 keys x 80B = 5120
#define PL0o 5120u
#define PH1o 10240u
#define PL1o 15360u
#define GH0o 20480u       // gT hi buf0: 32 ci x 144B = 4608
#define GL0o 25088u
#define GH1o 29696u
#define GL1o 34304u
#define WOo  38912u       // 64 x 33 floats = 8448
#define SMSZ 47360u

// ---------------------------------------------------------------------------
// Kernel 2: flash attention + out-proj + residual.
// grid = (NN/64, BB), 128 threads (4 warps x 16 query rows).
// ---------------------------------------------------------------------------
__global__ __launch_bounds__(128, 4)
void attn_kernel(const float* __restrict__ x,
                 const float* __restrict__ w_out,
                 const float* __restrict__ b_out,
                 float* __restrict__ out)
{
    __shared__ __align__(16) unsigned char SM[SMSZ];
    const unsigned shb = (unsigned)__cvta_generic_to_shared(SM);

    const int b    = blockIdx.y;
    const int n0b  = blockIdx.x * 64;
    const int tid  = threadIdx.x;
    const int warp = tid >> 5;
    const int lane = tid & 31;
    const int grp  = lane >> 2;
    const int t    = lane & 3;

    float* woS = (float*)(SM + WOo);
    for (int i = tid; i < CC * CI; i += 128) {
        int c = i >> 5, ci = i & 31;
        woS[c * 33 + ci] = w_out[i];
    }

    // ---- theta A fragments (bf16 hi/lo, pre-scaled by log2e) ------------
    const int row0 = warp * 16 + grp;
    unsigned aH[2][4], aL[2][4];
    {
        const __nv_bfloat16* thH = d_thH + ((size_t)(b * NN + n0b)) * CI;
        const __nv_bfloat16* thL = d_thL + ((size_t)(b * NN + n0b)) * CI;
        #pragma unroll
        for (int ch = 0; ch < 2; ++ch) {
            const int c0 = ch * 16 + 2 * t;
            aH[ch][0] = *(const unsigned*)(thH + (size_t)row0 * CI + c0);
            aH[ch][1] = *(const unsigned*)(thH + (size_t)(row0 + 8) * CI + c0);
            aH[ch][2] = *(const unsigned*)(thH + (size_t)row0 * CI + c0 + 8);
            aH[ch][3] = *(const unsigned*)(thH + (size_t)(row0 + 8) * CI + c0 + 8);
            aL[ch][0] = *(const unsigned*)(thL + (size_t)row0 * CI + c0);
            aL[ch][1] = *(const unsigned*)(thL + (size_t)(row0 + 8) * CI + c0);
            aL[ch][2] = *(const unsigned*)(thL + (size_t)row0 * CI + c0 + 8);
            aL[ch][3] = *(const unsigned*)(thL + (size_t)(row0 + 8) * CI + c0 + 8);
        }
    }

    float y[4][4];
    #pragma unroll
    for (int i = 0; i < 4; ++i)
        #pragma unroll
        for (int j = 0; j < 4; ++j) y[i][j] = 0.f;
    float rm0 = -1e30f, rm1 = -1e30f, rs0 = 0.f, rs1 = 0.f;

    const char* gphH = (const char*)(d_phH + ((size_t)b * MM) * CI);
    const char* gphL = (const char*)(d_phL + ((size_t)b * MM) * CI);
    const char* ggH  = (const char*)(d_gTH + (size_t)b * CI * MM);
    const char* ggL  = (const char*)(d_gTL + (size_t)b * CI * MM);

    auto copy_tile = [&](int mt, int buf) {
        const unsigned phO = buf ? PH1o : PH0o;
        const unsigned plO = buf ? PL1o : PL0o;
        const unsigned ghO = buf ? GH1o : GH0o;
        const unsigned glO = buf ? GL1o : GL0o;
        const char* ph = gphH + (size_t)mt * 64 * CI * 2;
        const char* pl = gphL + (size_t)mt * 64 * CI * 2;
        #pragma unroll
        for (int it = 0; it < 2; ++it) {
            int idx = tid + it * 128;          // 0..255
            int key = idx >> 2, c = idx & 3;
            cpa16(shb + phO + key * 80 + c * 16, ph + idx * 16);
            cpa16(shb + plO + key * 80 + c * 16, pl + idx * 16);
        }
        // gT rows: 32 ci x 128B (64 keys bf16); global row stride MM*2 bytes
        #pragma unroll
        for (int it = 0; it < 2; ++it) {
            int idx = tid + it * 128;          // 0..255
            int ci = idx >> 3, c = idx & 7;
            const size_t go = (size_t)ci * (MM * 2) + (size_t)mt * 128 + c * 16;
            cpa16(shb + ghO + ci * 144 + c * 16, ggH + go);
            cpa16(shb + glO + ci * 144 + c * 16, ggL + go);
        }
    };

    copy_tile(0, 0);
    cpcommit();

    const unsigned lmBase = (lane & 7) * 80 + (lane >> 3) * 16;   // phi ldsm
    // g ldsm: matrix j = lane>>3 -> (ncOff = j>>1, octet = j&1)
    const unsigned lmG = (unsigned)(((lane >> 4) * 8 + (lane & 7)) * 144 +
                                    ((lane >> 3) & 1) * 16);

    for (int mt = 0; mt < TILES; ++mt) {
        const int cur = mt & 1;
        if (mt + 1 < TILES) { copy_tile(mt + 1, cur ^ 1); cpcommit(); cpwait<1>(); }
        else                { cpwait<0>(); }
        __syncthreads();

        const unsigned phA = shb + (cur ? PH1o : PH0o) + lmBase;
        const unsigned plA = shb + (cur ? PL1o : PL0o) + lmBase;
        const unsigned gH  = shb + (cur ? GH1o : GH0o) + lmG;
        const unsigned gL  = shb + (cur ? GL1o : GL0o) + lmG;

        // ---- S = theta . phi^T  (split-bf16) ----------------------------
        float s[8][4];
        #pragma unroll
        for (int nt = 0; nt < 8; ++nt) {
            s[nt][0] = s[nt][1] = s[nt][2] = s[nt][3] = 0.f;
            uint4 bh = ldsm4(phA + nt * 640);
            uint4 bl = ldsm4(plA + nt * 640);
            mma16(s[nt], aH[0], bh.x, bh.y);
            mma16(s[nt], aH[1], bh.z, bh.w);
            mma16(s[nt], aL[0], bh.x, bh.y);
            mma16(s[nt], aL[1], bh.z, bh.w);
            mma16(s[nt], aH[0], bl.x, bl.y);
            mma16(s[nt], aH[1], bl.z, bl.w);
        }

        // ---- online softmax (log2 domain) -------------------------------
        float m0 = s[0][0], m1 = s[0][2];
        #pragma unroll
        for (int nt = 0; nt < 8; ++nt) {
            m0 = fmaxf(m0, fmaxf(s[nt][0], s[nt][1]));
            m1 = fmaxf(m1, fmaxf(s[nt][2], s[nt][3]));
        }
        m0 = fmaxf(m0, __shfl_xor_sync(0xffffffffu, m0, 1));
        m0 = fmaxf(m0, __shfl_xor_sync(0xffffffffu, m0, 2));
        m1 = fmaxf(m1, __shfl_xor_sync(0xffffffffu, m1, 1));
        m1 = fmaxf(m1, __shfl_xor_sync(0xffffffffu, m1, 2));

        const float nm0 = fmaxf(rm0, m0);
        const float nm1 = fmaxf(rm1, m1);
        const float sc0 = exp2f(rm0 - nm0);
        const float sc1 = exp2f(rm1 - nm1);
        rm0 = nm0; rm1 = nm1;
        rs0 *= sc0; rs1 *= sc1;
        #pragma unroll
        for (int nc = 0; nc < 4; ++nc) {
            y[nc][0] *= sc0; y[nc][1] *= sc0;
            y[nc][2] *= sc1; y[nc][3] *= sc1;
        }

        // ---- P = 2^(S-m);  y += pH@gH + pH@gL + pL@gH -------------------
        #pragma unroll
        for (int kc = 0; kc < 4; ++kc) {
            const int nt0 = 2 * kc, nt1 = 2 * kc + 1;
            float p00 = exp2f(s[nt0][0] - nm0);
            float p01 = exp2f(s[nt0][1] - nm0);
            float p02 = exp2f(s[nt0][2] - nm1);
            float p03 = exp2f(s[nt0][3] - nm1);
            float p10 = exp2f(s[nt1][0] - nm0);
            float p11 = exp2f(s[nt1][1] - nm0);
            float p12 = exp2f(s[nt1][2] - nm1);
            float p13 = exp2f(s[nt1][3] - nm1);
            rs0 += (p00 + p01) + (p10 + p11);
            rs1 += (p02 + p03) + (p12 + p13);

            const unsigned u00 = __float_as_uint(p00), u01 = __float_as_uint(p01);
            const unsigned u02 = __float_as_uint(p02), u03 = __float_as_uint(p03);
            const unsigned u10 = __float_as_uint(p10), u11 = __float_as_uint(p11);
            const unsigned u12 = __float_as_uint(p12), u13 = __float_as_uint(p13);

            // A-frag hi: truncated-bf16 (top 16 bits) via PRMT
            unsigned pa[4];
            pa[0] = prmt7632(u00, u01);
            pa[1] = prmt7632(u02, u03);
            pa[2] = prmt7632(u10, u11);
            pa[3] = prmt7632(u12, u13);

            // A-frag lo: residual, rounded bf16x2
            unsigned pl[4];
            pl[0] = pkbf2(p00 - __uint_as_float(u00 & 0xffff0000u),
                          p01 - __uint_as_float(u01 & 0xffff0000u));
            pl[1] = pkbf2(p02 - __uint_as_float(u02 & 0xffff0000u),
                          p03 - __uint_as_float(u03 & 0xffff0000u));
            pl[2] = pkbf2(p10 - __uint_as_float(u10 & 0xffff0000u),
                          p11 - __uint_as_float(u11 & 0xffff0000u));
            pl[3] = pkbf2(p12 - __uint_as_float(u12 & 0xffff0000u),
                          p13 - __uint_as_float(u13 & 0xffff0000u));

            // g B-frags: ldsm4 -> (nc, b0/b1) pairs
            uint4 h0 = ldsm4(gH + kc * 32);            // nc 0,1
            uint4 h1 = ldsm4(gH + 2304 + kc * 32);     // nc 2,3
            uint4 l0 = ldsm4(gL + kc * 32);
            uint4 l1 = ldsm4(gL + 2304 + kc * 32);

            mma16(y[0], pa, h0.x, h0.y);
            mma16(y[1], pa, h0.z, h0.w);
            mma16(y[2], pa, h1.x, h1.y);
            mma16(y[3], pa, h1.z, h1.w);
            mma16(y[0], pa, l0.x, l0.y);
            mma16(y[1], pa, l0.z, l0.w);
            mma16(y[2], pa, l1.x, l1.y);
            mma16(y[3], pa, l1.z, l1.w);
            mma16(y[0], pl, h0.x, h0.y);
            mma16(y[1], pl, h0.z, h0.w);
            mma16(y[2], pl, h1.x, h1.y);
            mma16(y[3], pl, h1.z, h1.w);
        }
        __syncthreads();
    }

    // combine partial sums across the 4 lanes of each row group
    rs0 += __shfl_xor_sync(0xffffffffu, rs0, 1);
    rs0 += __shfl_xor_sync(0xffffffffu, rs0, 2);
    rs1 += __shfl_xor_sync(0xffffffffu, rs1, 1);
    rs1 += __shfl_xor_sync(0xffffffffu, rs1, 2);
    const float inv0 = 1.0f / rs0;
    const float inv1 = 1.0f / rs1;

    float* ySm = (float*)(SM + GH0o);      // reuse g buffers (18432 B >= 8448)
    #pragma unroll
    for (int nc = 0; nc < 4; ++nc) {
        ySm[row0 * 33 + nc * 8 + 2 * t]           = y[nc][0] * inv0;
        ySm[row0 * 33 + nc * 8 + 2 * t + 1]       = y[nc][1] * inv0;
        ySm[(row0 + 8) * 33 + nc * 8 + 2 * t]     = y[nc][2] * inv1;
        ySm[(row0 + 8) * 33 + nc * 8 + 2 * t + 1] = y[nc][3] * inv1;
    }
    __syncthreads();

    // epilogue: out[b][c][n] = y . w_out[c] + b_out[c] + x[b][c][n]
    {
        const int row  = tid >> 1;
        const int half = tid & 1;
        float yv[32];
        #pragma unroll
        for (int i = 0; i < 32; ++i) yv[i] = ySm[row * 33 + i];
        const int n = n0b + row;
        #pragma unroll
        for (int j = 0; j < 32; ++j) {
            const int c = half * 32 + j;
            float acc = b_out[c];
            #pragma unroll
            for (int ci = 0; ci < 32; ++ci)
                acc = fmaf(woS[c * 33 + ci], yv[ci], acc);
            const size_t oi = ((size_t)(b * CC + c)) * NN + n;
            out[oi] = acc + x[oi];
        }
    }
}

// ---------------------------------------------------------------------------
extern "C" void kernel_launch(void* const* d_in, const int* in_sizes, int n_in,
                              void* d_out, int out_size)
{
    const float* x  = (const float*)d_in[0];
    const float* wt = (const float*)d_in[1];
    const float* bt = (const float*)d_in[2];
    const float* wp = (const float*)d_in[3];
    const float* bp = (const float*)d_in[4];
    const float* wg = (const float*)d_in[5];
    const float* bg = (const float*)d_in[6];
    const float* wo = (const float*)d_in[7];
    const float* bo = (const float*)d_in[8];
    float* out = (float*)d_out;

    dim3 grid(NN / 64, BB);
    proj_kernel<<<grid, 256>>>(x, wt, bt, wp, bp, wg, bg);
    attn_kernel<<<grid, 128>>>(x, wo, bo, out);
}

// round 5
// speedup vs baseline: 8.3367x; 1.5494x over previous
#include <cuda_runtime.h>
#include <cuda_fp16.h>
#include <cuda_bf16.h>

// ---------------------------------------------------------------------------
// NonlocalBlock: B=4, C=64, N=9216, Ci=32, M=4608
// Round 5: fp16 everywhere. S = thH*phi + thL*phi (theta split fp16, phi
// single fp16). P@g single fp16. Halves MMA count, LDSM count, smem, staging.
// ---------------------------------------------------------------------------

#define BB 4
#define CC 64
#define NN 9216
#define CI 32
#define MM 4608
#define TILES (MM / 64)
#define LOG2E 1.4426950408889634f

// scratch (__device__ globals: allocation-free rule)
__device__ __half d_thH[(size_t)BB * NN * CI];   // theta*log2e hi (fp16)
__device__ __half d_thL[(size_t)BB * NN * CI];   // theta*log2e lo (fp16)
__device__ __half d_ph [(size_t)BB * MM * CI];   // phi (fp16 rn)
__device__ __half d_gT [(size_t)BB * CI * MM];   // g transposed (fp16 rn)

// D += A(16x16) * B(16x8), fp16 in / fp32 accum
__device__ __forceinline__ void mma16(float* c, const unsigned* a,
                                      unsigned b0, unsigned b1) {
    asm volatile(
        "mma.sync.aligned.m16n8k16.row.col.f32.f16.f16.f32 "
        "{%0,%1,%2,%3}, {%4,%5,%6,%7}, {%8,%9}, {%0,%1,%2,%3};"
        : "+f"(c[0]), "+f"(c[1]), "+f"(c[2]), "+f"(c[3])
        : "r"(a[0]), "r"(a[1]), "r"(a[2]), "r"(a[3]), "r"(b0), "r"(b1));
}
__device__ __forceinline__ uint4 ldsm4(unsigned a) {
    uint4 r;
    asm volatile("ldmatrix.sync.aligned.m8n8.x4.shared.b16 {%0,%1,%2,%3}, [%4];"
                 : "=r"(r.x), "=r"(r.y), "=r"(r.z), "=r"(r.w) : "r"(a));
    return r;
}
__device__ __forceinline__ void cpa16(unsigned s, const void* g) {
    asm volatile("cp.async.ca.shared.global [%0], [%1], 16;" :: "r"(s), "l"(g));
}
__device__ __forceinline__ void cpcommit() { asm volatile("cp.async.commit_group;"); }
template <int N> __device__ __forceinline__ void cpwait() {
    asm volatile("cp.async.wait_group %0;" :: "n"(N));
}
// pack {lo=f16(lo), hi=f16(hi)}   (cvt.rn.f16x2.f32 d, a, b -> d.hi=a, d.lo=b)
__device__ __forceinline__ unsigned pkhf2(float lo, float hi) {
    unsigned d; asm("cvt.rn.f16x2.f32 %0, %1, %2;" : "=r"(d) : "f"(hi), "f"(lo));
    return d;
}

// ---------------------------------------------------------------------------
// Kernel 1: projections + maxpool, fp16 outputs (theta pre-scaled by log2e,
// split hi/lo). grid = (NN/64, BB), 256 threads (8 warps x 8 pos; lane = ci).
// ---------------------------------------------------------------------------
__global__ __launch_bounds__(256, 2)
void proj_kernel(const float* __restrict__ x,
                 const float* __restrict__ wt, const float* __restrict__ bt,
                 const float* __restrict__ wp, const float* __restrict__ bp,
                 const float* __restrict__ wg, const float* __restrict__ bg)
{
    __shared__ float xs[64][68];
    __shared__ float wts[64][32];
    __shared__ float wps[64][32];
    __shared__ float wgs[64][32];

    const int b  = blockIdx.y;
    const int n0 = blockIdx.x * 64;
    const int tid = threadIdx.x;

    for (int i = tid; i < CI * CC; i += 256) {
        int ci = i >> 6, c = i & 63;
        wts[c][ci] = wt[i];
        wps[c][ci] = wp[i];
        wgs[c][ci] = wg[i];
    }
    for (int i = tid; i < 64 * 64; i += 256) {
        int c = i >> 6, nl = i & 63;
        xs[nl][c] = x[((size_t)(b * CC + c)) * NN + n0 + nl];
    }
    __syncthreads();

    const int ci = tid & 31;
    const int g8 = tid >> 5;
    float at[8], ap[8], ag[8];
    #pragma unroll
    for (int i = 0; i < 8; ++i) { at[i] = 0.f; ap[i] = 0.f; ag[i] = 0.f; }

    #pragma unroll
    for (int cb = 0; cb < 64; cb += 8) {
        float wtr[8], wpr[8], wgr[8];
        #pragma unroll
        for (int k = 0; k < 8; ++k) {
            wtr[k] = wts[cb + k][ci];
            wpr[k] = wps[cb + k][ci];
            wgr[k] = wgs[cb + k][ci];
        }
        #pragma unroll
        for (int i = 0; i < 8; ++i) {
            const int nl = g8 * 8 + i;
            float4 v0 = *(const float4*)&xs[nl][cb];
            float4 v1 = *(const float4*)&xs[nl][cb + 4];
            at[i] = fmaf(v0.x, wtr[0], at[i]); ap[i] = fmaf(v0.x, wpr[0], ap[i]); ag[i] = fmaf(v0.x, wgr[0], ag[i]);
            at[i] = fmaf(v0.y, wtr[1], at[i]); ap[i] = fmaf(v0.y, wpr[1], ap[i]); ag[i] = fmaf(v0.y, wgr[1], ag[i]);
            at[i] = fmaf(v0.z, wtr[2], at[i]); ap[i] = fmaf(v0.z, wpr[2], ap[i]); ag[i] = fmaf(v0.z, wgr[2], ag[i]);
            at[i] = fmaf(v0.w, wtr[3], at[i]); ap[i] = fmaf(v0.w, wpr[3], ap[i]); ag[i] = fmaf(v0.w, wgr[3], ag[i]);
            at[i] = fmaf(v1.x, wtr[4], at[i]); ap[i] = fmaf(v1.x, wpr[4], ap[i]); ag[i] = fmaf(v1.x, wgr[4], ag[i]);
            at[i] = fmaf(v1.y, wtr[5], at[i]); ap[i] = fmaf(v1.y, wpr[5], ap[i]); ag[i] = fmaf(v1.y, wgr[5], ag[i]);
            at[i] = fmaf(v1.z, wtr[6], at[i]); ap[i] = fmaf(v1.z, wpr[6], ap[i]); ag[i] = fmaf(v1.z, wgr[6], ag[i]);
            at[i] = fmaf(v1.w, wtr[7], at[i]); ap[i] = fmaf(v1.w, wpr[7], ap[i]); ag[i] = fmaf(v1.w, wgr[7], ag[i]);
        }
    }

    const float bth = bt[ci], bph = bp[ci], bgg = bg[ci];
    float prev_p = 0.f, prev_g = 0.f;
    #pragma unroll
    for (int i = 0; i < 8; ++i) {
        const int nl = g8 * 8 + i;
        const float tv = (at[i] + bth) * LOG2E;
        const float pv0 = ap[i] + bph;
        const float gv0 = ag[i] + bgg;
        {
            const size_t ti = ((size_t)(b * NN + n0 + nl)) * CI + ci;
            __half h = __float2half_rn(tv);
            d_thH[ti] = h;
            d_thL[ti] = __float2half_rn(tv - __half2float(h));
        }
        if (i & 1) {
            const int m = (n0 + nl) >> 1;
            d_ph[((size_t)(b * MM + m)) * CI + ci] = __float2half_rn(fmaxf(prev_p, pv0));
            d_gT[((size_t)(b * CI + ci)) * MM + m] = __float2half_rn(fmaxf(prev_g, gv0));
        } else {
            prev_p = pv0; prev_g = gv0;
        }
    }
}

// ---------------------------------------------------------------------------
// smem byte offsets
// ---------------------------------------------------------------------------
#define PH0o 0u           // phi buf0: 64 keys x 80B rows = 5120
#define PH1o 5120u
#define G0o  10240u       // gT buf0: 32 ci x 144B rows = 4608
#define G1o  14848u
#define WOo  19456u       // 64 x 33 floats = 8448
#define SMSZ 27904u

// ---------------------------------------------------------------------------
// Kernel 2: flash attention + out-proj + residual.
// grid = (NN/64, BB), 128 threads (4 warps x 16 query rows).
// ---------------------------------------------------------------------------
__global__ __launch_bounds__(128, 4)
void attn_kernel(const float* __restrict__ x,
                 const float* __restrict__ w_out,
                 const float* __restrict__ b_out,
                 float* __restrict__ out)
{
    __shared__ __align__(16) unsigned char SM[SMSZ];
    const unsigned shb = (unsigned)__cvta_generic_to_shared(SM);

    const int b    = blockIdx.y;
    const int n0b  = blockIdx.x * 64;
    const int tid  = threadIdx.x;
    const int warp = tid >> 5;
    const int lane = tid & 31;
    const int grp  = lane >> 2;
    const int t    = lane & 3;

    float* woS = (float*)(SM + WOo);
    for (int i = tid; i < CC * CI; i += 128) {
        int c = i >> 5, ci = i & 31;
        woS[c * 33 + ci] = w_out[i];
    }

    // ---- theta A fragments (fp16 hi/lo, pre-scaled by log2e) ------------
    const int row0 = warp * 16 + grp;
    unsigned aH[2][4], aL[2][4];
    {
        const __half* thH = d_thH + ((size_t)(b * NN + n0b)) * CI;
        const __half* thL = d_thL + ((size_t)(b * NN + n0b)) * CI;
        #pragma unroll
        for (int ch = 0; ch < 2; ++ch) {
            const int c0 = ch * 16 + 2 * t;
            aH[ch][0] = *(const unsigned*)(thH + (size_t)row0 * CI + c0);
            aH[ch][1] = *(const unsigned*)(thH + (size_t)(row0 + 8) * CI + c0);
            aH[ch][2] = *(const unsigned*)(thH + (size_t)row0 * CI + c0 + 8);
            aH[ch][3] = *(const unsigned*)(thH + (size_t)(row0 + 8) * CI + c0 + 8);
            aL[ch][0] = *(const unsigned*)(thL + (size_t)row0 * CI + c0);
            aL[ch][1] = *(const unsigned*)(thL + (size_t)(row0 + 8) * CI + c0);
            aL[ch][2] = *(const unsigned*)(thL + (size_t)row0 * CI + c0 + 8);
            aL[ch][3] = *(const unsigned*)(thL + (size_t)(row0 + 8) * CI + c0 + 8);
        }
    }

    float y[4][4];
    #pragma unroll
    for (int i = 0; i < 4; ++i)
        #pragma unroll
        for (int j = 0; j < 4; ++j) y[i][j] = 0.f;
    float rm0 = -1e30f, rm1 = -1e30f, rs0 = 0.f, rs1 = 0.f;

    const char* gph = (const char*)(d_ph + ((size_t)b * MM) * CI);
    const char* ggT = (const char*)(d_gT + (size_t)b * CI * MM);

    auto copy_tile = [&](int mt, int buf) {
        const unsigned phO = buf ? PH1o : PH0o;
        const unsigned gO  = buf ? G1o : G0o;
        const char* ph = gph + (size_t)mt * 64 * CI * 2;
        #pragma unroll
        for (int it = 0; it < 2; ++it) {
            int idx = tid + it * 128;          // 0..255
            int key = idx >> 2, c = idx & 3;
            cpa16(shb + phO + key * 80 + c * 16, ph + idx * 16);
        }
        #pragma unroll
        for (int it = 0; it < 2; ++it) {
            int idx = tid + it * 128;          // 0..255
            int ci = idx >> 3, c = idx & 7;
            cpa16(shb + gO + ci * 144 + c * 16,
                  ggT + (size_t)ci * (MM * 2) + (size_t)mt * 128 + c * 16);
        }
    };

    copy_tile(0, 0);
    cpcommit();

    const unsigned lmBase = (lane & 7) * 80 + (lane >> 3) * 16;   // phi ldsm
    const unsigned lmG = (unsigned)(((lane >> 4) * 8 + (lane & 7)) * 144 +
                                    ((lane >> 3) & 1) * 16);

    for (int mt = 0; mt < TILES; ++mt) {
        const int cur = mt & 1;
        if (mt + 1 < TILES) { copy_tile(mt + 1, cur ^ 1); cpcommit(); cpwait<1>(); }
        else                { cpwait<0>(); }
        __syncthreads();

        const unsigned phA = shb + (cur ? PH1o : PH0o) + lmBase;
        const unsigned gA  = shb + (cur ? G1o : G0o) + lmG;

        // ---- S = (thH + thL) . phi^T  (2 terms) -------------------------
        float s[8][4];
        #pragma unroll
        for (int nt = 0; nt < 8; ++nt) {
            s[nt][0] = s[nt][1] = s[nt][2] = s[nt][3] = 0.f;
            uint4 bh = ldsm4(phA + nt * 640);
            mma16(s[nt], aH[0], bh.x, bh.y);
            mma16(s[nt], aH[1], bh.z, bh.w);
            mma16(s[nt], aL[0], bh.x, bh.y);
            mma16(s[nt], aL[1], bh.z, bh.w);
        }

        // ---- online softmax (log2 domain) -------------------------------
        float m0 = s[0][0], m1 = s[0][2];
        #pragma unroll
        for (int nt = 0; nt < 8; ++nt) {
            m0 = fmaxf(m0, fmaxf(s[nt][0], s[nt][1]));
            m1 = fmaxf(m1, fmaxf(s[nt][2], s[nt][3]));
        }
        m0 = fmaxf(m0, __shfl_xor_sync(0xffffffffu, m0, 1));
        m0 = fmaxf(m0, __shfl_xor_sync(0xffffffffu, m0, 2));
        m1 = fmaxf(m1, __shfl_xor_sync(0xffffffffu, m1, 1));
        m1 = fmaxf(m1, __shfl_xor_sync(0xffffffffu, m1, 2));

        const float nm0 = fmaxf(rm0, m0);
        const float nm1 = fmaxf(rm1, m1);
        const float sc0 = exp2f(rm0 - nm0);
        const float sc1 = exp2f(rm1 - nm1);
        rm0 = nm0; rm1 = nm1;
        rs0 *= sc0; rs1 *= sc1;
        #pragma unroll
        for (int nc = 0; nc < 4; ++nc) {
            y[nc][0] *= sc0; y[nc][1] *= sc0;
            y[nc][2] *= sc1; y[nc][3] *= sc1;
        }

        // ---- P = 2^(S-m) (fp16);  y += P @ g ----------------------------
        #pragma unroll
        for (int kc = 0; kc < 4; ++kc) {
            const int nt0 = 2 * kc, nt1 = 2 * kc + 1;
            float p00 = exp2f(s[nt0][0] - nm0);
            float p01 = exp2f(s[nt0][1] - nm0);
            float p02 = exp2f(s[nt0][2] - nm1);
            float p03 = exp2f(s[nt0][3] - nm1);
            float p10 = exp2f(s[nt1][0] - nm0);
            float p11 = exp2f(s[nt1][1] - nm0);
            float p12 = exp2f(s[nt1][2] - nm1);
            float p13 = exp2f(s[nt1][3] - nm1);
            rs0 += (p00 + p01) + (p10 + p11);
            rs1 += (p02 + p03) + (p12 + p13);

            unsigned pa[4];
            pa[0] = pkhf2(p00, p01);
            pa[1] = pkhf2(p02, p03);
            pa[2] = pkhf2(p10, p11);
            pa[3] = pkhf2(p12, p13);

            uint4 h0 = ldsm4(gA + kc * 32);            // nc 0,1
            uint4 h1 = ldsm4(gA + 2304 + kc * 32);     // nc 2,3
            mma16(y[0], pa, h0.x, h0.y);
            mma16(y[1], pa, h0.z, h0.w);
            mma16(y[2], pa, h1.x, h1.y);
            mma16(y[3], pa, h1.z, h1.w);
        }
        __syncthreads();
    }

    // combine partial sums across the 4 lanes of each row group
    rs0 += __shfl_xor_sync(0xffffffffu, rs0, 1);
    rs0 += __shfl_xor_sync(0xffffffffu, rs0, 2);
    rs1 += __shfl_xor_sync(0xffffffffu, rs1, 1);
    rs1 += __shfl_xor_sync(0xffffffffu, rs1, 2);
    const float inv0 = 1.0f / rs0;
    const float inv1 = 1.0f / rs1;

    float* ySm = (float*)(SM + G0o);       // reuse g buffers (9216 B >= 8448)
    #pragma unroll
    for (int nc = 0; nc < 4; ++nc) {
        ySm[row0 * 33 + nc * 8 + 2 * t]           = y[nc][0] * inv0;
        ySm[row0 * 33 + nc * 8 + 2 * t + 1]       = y[nc][1] * inv0;
        ySm[(row0 + 8) * 33 + nc * 8 + 2 * t]     = y[nc][2] * inv1;
        ySm[(row0 + 8) * 33 + nc * 8 + 2 * t + 1] = y[nc][3] * inv1;
    }
    __syncthreads();

    // epilogue: out[b][c][n] = y . w_out[c] + b_out[c] + x[b][c][n]
    {
        const int row  = tid >> 1;
        const int half = tid & 1;
        float yv[32];
        #pragma unroll
        for (int i = 0; i < 32; ++i) yv[i] = ySm[row * 33 + i];
        const int n = n0b + row;
        #pragma unroll
        for (int j = 0; j < 32; ++j) {
            const int c = half * 32 + j;
            float acc = b_out[c];
            #pragma unroll
            for (int ci = 0; ci < 32; ++ci)
                acc = fmaf(woS[c * 33 + ci], yv[ci], acc);
            const size_t oi = ((size_t)(b * CC + c)) * NN + n;
            out[oi] = acc + x[oi];
        }
    }
}

// ---------------------------------------------------------------------------
extern "C" void kernel_launch(void* const* d_in, const int* in_sizes, int n_in,
                              void* d_out, int out_size)
{
    const float* x  = (const float*)d_in[0];
    const float* wt = (const float*)d_in[1];
    const float* bt = (const float*)d_in[2];
    const float* wp = (const float*)d_in[3];
    const float* bp = (const float*)d_in[4];
    const float* wg = (const float*)d_in[5];
    const float* bg = (const float*)d_in[6];
    const float* wo = (const float*)d_in[7];
    const float* bo = (const float*)d_in[8];
    float* out = (float*)d_out;

    dim3 grid(NN / 64, BB);
    proj_kernel<<<grid, 256>>>(x, wt, bt, wp, bp, wg, bg);
    attn_kernel<<<grid, 128>>>(x, wo, bo, out);
}

// round 6
// speedup vs baseline: 8.8062x; 1.0563x over previous
#include <cuda_runtime.h>
#include <cuda_fp16.h>
#include <cuda_bf16.h>

// ---------------------------------------------------------------------------
// NonlocalBlock: B=4, C=64, N=9216, Ci=32, M=4608
// Round 6: fp16 flash-attn; ex2.approx.f16x2 for P; row-sum via ones-column
// MMA (tensor pipe); zero-C first MMA. theta split fp16 hi/lo, phi/g fp16.
// ---------------------------------------------------------------------------

#define BB 4
#define CC 64
#define NN 9216
#define CI 32
#define MM 4608
#define TILES (MM / 64)
#define LOG2E 1.4426950408889634f

// scratch (__device__ globals: allocation-free rule)
__device__ __half d_thH[(size_t)BB * NN * CI];   // theta*log2e hi (fp16)
__device__ __half d_thL[(size_t)BB * NN * CI];   // theta*log2e lo (fp16)
__device__ __half d_ph [(size_t)BB * MM * CI];   // phi (fp16 rn)
__device__ __half d_gT [(size_t)BB * CI * MM];   // g transposed (fp16 rn)

// D += A(16x16) * B(16x8), fp16 in / fp32 accum
__device__ __forceinline__ void mma16(float* c, const unsigned* a,
                                      unsigned b0, unsigned b1) {
    asm volatile(
        "mma.sync.aligned.m16n8k16.row.col.f32.f16.f16.f32 "
        "{%0,%1,%2,%3}, {%4,%5,%6,%7}, {%8,%9}, {%0,%1,%2,%3};"
        : "+f"(c[0]), "+f"(c[1]), "+f"(c[2]), "+f"(c[3])
        : "r"(a[0]), "r"(a[1]), "r"(a[2]), "r"(a[3]), "r"(b0), "r"(b1));
}
// D = A*B + 0   (no accumulator read -> kills zero-init MOVs)
__device__ __forceinline__ void mma16z(float* d, const unsigned* a,
                                       unsigned b0, unsigned b1) {
    asm volatile(
        "mma.sync.aligned.m16n8k16.row.col.f32.f16.f16.f32 "
        "{%0,%1,%2,%3}, {%4,%5,%6,%7}, {%8,%9}, {%10,%11,%12,%13};"
        : "=f"(d[0]), "=f"(d[1]), "=f"(d[2]), "=f"(d[3])
        : "r"(a[0]), "r"(a[1]), "r"(a[2]), "r"(a[3]), "r"(b0), "r"(b1),
          "f"(0.f), "f"(0.f), "f"(0.f), "f"(0.f));
}
__device__ __forceinline__ uint4 ldsm4(unsigned a) {
    uint4 r;
    asm volatile("ldmatrix.sync.aligned.m8n8.x4.shared.b16 {%0,%1,%2,%3}, [%4];"
                 : "=r"(r.x), "=r"(r.y), "=r"(r.z), "=r"(r.w) : "r"(a));
    return r;
}
__device__ __forceinline__ void cpa16(unsigned s, const void* g) {
    asm volatile("cp.async.ca.shared.global [%0], [%1], 16;" :: "r"(s), "l"(g));
}
__device__ __forceinline__ void cpcommit() { asm volatile("cp.async.commit_group;"); }
template <int N> __device__ __forceinline__ void cpwait() {
    asm volatile("cp.async.wait_group %0;" :: "n"(N));
}
// pack {lo=f16(lo), hi=f16(hi)}
__device__ __forceinline__ unsigned pkhf2(float lo, float hi) {
    unsigned d; asm("cvt.rn.f16x2.f32 %0, %1, %2;" : "=r"(d) : "f"(hi), "f"(lo));
    return d;
}
// 2^x elementwise on f16x2
__device__ __forceinline__ unsigned h2ex2(unsigned x) {
    unsigned d; asm("ex2.approx.f16x2 %0, %1;" : "=r"(d) : "r"(x));
    return d;
}

// ---------------------------------------------------------------------------
// Kernel 1: projections + maxpool, fp16 outputs (theta pre-scaled by log2e,
// split hi/lo). grid = (NN/64, BB), 256 threads (8 warps x 8 pos; lane = ci).
// ---------------------------------------------------------------------------
__global__ __launch_bounds__(256, 2)
void proj_kernel(const float* __restrict__ x,
                 const float* __restrict__ wt, const float* __restrict__ bt,
                 const float* __restrict__ wp, const float* __restrict__ bp,
                 const float* __restrict__ wg, const float* __restrict__ bg)
{
    __shared__ float xs[64][68];
    __shared__ float wts[64][32];
    __shared__ float wps[64][32];
    __shared__ float wgs[64][32];

    const int b  = blockIdx.y;
    const int n0 = blockIdx.x * 64;
    const int tid = threadIdx.x;

    for (int i = tid; i < CI * CC; i += 256) {
        int ci = i >> 6, c = i & 63;
        wts[c][ci] = wt[i];
        wps[c][ci] = wp[i];
        wgs[c][ci] = wg[i];
    }
    for (int i = tid; i < 64 * 64; i += 256) {
        int c = i >> 6, nl = i & 63;
        xs[nl][c] = x[((size_t)(b * CC + c)) * NN + n0 + nl];
    }
    __syncthreads();

    const int ci = tid & 31;
    const int g8 = tid >> 5;
    float at[8], ap[8], ag[8];
    #pragma unroll
    for (int i = 0; i < 8; ++i) { at[i] = 0.f; ap[i] = 0.f; ag[i] = 0.f; }

    #pragma unroll
    for (int cb = 0; cb < 64; cb += 8) {
        float wtr[8], wpr[8], wgr[8];
        #pragma unroll
        for (int k = 0; k < 8; ++k) {
            wtr[k] = wts[cb + k][ci];
            wpr[k] = wps[cb + k][ci];
            wgr[k] = wgs[cb + k][ci];
        }
        #pragma unroll
        for (int i = 0; i < 8; ++i) {
            const int nl = g8 * 8 + i;
            float4 v0 = *(const float4*)&xs[nl][cb];
            float4 v1 = *(const float4*)&xs[nl][cb + 4];
            at[i] = fmaf(v0.x, wtr[0], at[i]); ap[i] = fmaf(v0.x, wpr[0], ap[i]); ag[i] = fmaf(v0.x, wgr[0], ag[i]);
            at[i] = fmaf(v0.y, wtr[1], at[i]); ap[i] = fmaf(v0.y, wpr[1], ap[i]); ag[i] = fmaf(v0.y, wgr[1], ag[i]);
            at[i] = fmaf(v0.z, wtr[2], at[i]); ap[i] = fmaf(v0.z, wpr[2], ap[i]); ag[i] = fmaf(v0.z, wgr[2], ag[i]);
            at[i] = fmaf(v0.w, wtr[3], at[i]); ap[i] = fmaf(v0.w, wpr[3], ap[i]); ag[i] = fmaf(v0.w, wgr[3], ag[i]);
            at[i] = fmaf(v1.x, wtr[4], at[i]); ap[i] = fmaf(v1.x, wpr[4], ap[i]); ag[i] = fmaf(v1.x, wgr[4], ag[i]);
            at[i] = fmaf(v1.y, wtr[5], at[i]); ap[i] = fmaf(v1.y, wpr[5], ap[i]); ag[i] = fmaf(v1.y, wgr[5], ag[i]);
            at[i] = fmaf(v1.z, wtr[6], at[i]); ap[i] = fmaf(v1.z, wpr[6], ap[i]); ag[i] = fmaf(v1.z, wgr[6], ag[i]);
            at[i] = fmaf(v1.w, wtr[7], at[i]); ap[i] = fmaf(v1.w, wpr[7], ap[i]); ag[i] = fmaf(v1.w, wgr[7], ag[i]);
        }
    }

    const float bth = bt[ci], bph = bp[ci], bgg = bg[ci];
    float prev_p = 0.f, prev_g = 0.f;
    #pragma unroll
    for (int i = 0; i < 8; ++i) {
        const int nl = g8 * 8 + i;
        const float tv = (at[i] + bth) * LOG2E;
        const float pv0 = ap[i] + bph;
        const float gv0 = ag[i] + bgg;
        {
            const size_t ti = ((size_t)(b * NN + n0 + nl)) * CI + ci;
            __half h = __float2half_rn(tv);
            d_thH[ti] = h;
            d_thL[ti] = __float2half_rn(tv - __half2float(h));
        }
        if (i & 1) {
            const int m = (n0 + nl) >> 1;
            d_ph[((size_t)(b * MM + m)) * CI + ci] = __float2half_rn(fmaxf(prev_p, pv0));
            d_gT[((size_t)(b * CI + ci)) * MM + m] = __float2half_rn(fmaxf(prev_g, gv0));
        } else {
            prev_p = pv0; prev_g = gv0;
        }
    }
}

// ---------------------------------------------------------------------------
// smem byte offsets
// ---------------------------------------------------------------------------
#define PH0o 0u           // phi buf0: 64 keys x 80B rows = 5120
#define PH1o 5120u
#define G0o  10240u       // gT buf0: 32 ci x 144B rows = 4608
#define G1o  14848u
#define WOo  19456u       // 64 x 33 floats = 8448
#define SMSZ 27904u

// ---------------------------------------------------------------------------
// Kernel 2: flash attention + out-proj + residual.
// grid = (NN/64, BB), 128 threads (4 warps x 16 query rows).
// ---------------------------------------------------------------------------
__global__ __launch_bounds__(128, 4)
void attn_kernel(const float* __restrict__ x,
                 const float* __restrict__ w_out,
                 const float* __restrict__ b_out,
                 float* __restrict__ out)
{
    __shared__ __align__(16) unsigned char SM[SMSZ];
    const unsigned shb = (unsigned)__cvta_generic_to_shared(SM);

    const int b    = blockIdx.y;
    const int n0b  = blockIdx.x * 64;
    const int tid  = threadIdx.x;
    const int warp = tid >> 5;
    const int lane = tid & 31;
    const int grp  = lane >> 2;
    const int t    = lane & 3;

    float* woS = (float*)(SM + WOo);
    for (int i = tid; i < CC * CI; i += 128) {
        int c = i >> 5, ci = i & 31;
        woS[c * 33 + ci] = w_out[i];
    }

    // ---- theta A fragments (fp16 hi/lo, pre-scaled by log2e) ------------
    const int row0 = warp * 16 + grp;
    unsigned aH[2][4], aL[2][4];
    {
        const __half* thH = d_thH + ((size_t)(b * NN + n0b)) * CI;
        const __half* thL = d_thL + ((size_t)(b * NN + n0b)) * CI;
        #pragma unroll
        for (int ch = 0; ch < 2; ++ch) {
            const int c0 = ch * 16 + 2 * t;
            aH[ch][0] = *(const unsigned*)(thH + (size_t)row0 * CI + c0);
            aH[ch][1] = *(const unsigned*)(thH + (size_t)(row0 + 8) * CI + c0);
            aH[ch][2] = *(const unsigned*)(thH + (size_t)row0 * CI + c0 + 8);
            aH[ch][3] = *(const unsigned*)(thH + (size_t)(row0 + 8) * CI + c0 + 8);
            aL[ch][0] = *(const unsigned*)(thL + (size_t)row0 * CI + c0);
            aL[ch][1] = *(const unsigned*)(thL + (size_t)(row0 + 8) * CI + c0);
            aL[ch][2] = *(const unsigned*)(thL + (size_t)row0 * CI + c0 + 8);
            aL[ch][3] = *(const unsigned*)(thL + (size_t)(row0 + 8) * CI + c0 + 8);
        }
    }

    float y[4][4];
    #pragma unroll
    for (int i = 0; i < 4; ++i)
        #pragma unroll
        for (int j = 0; j < 4; ++j) y[i][j] = 0.f;
    float y5[4] = {0.f, 0.f, 0.f, 0.f};          // ones-column row sums
    float rm0 = -1e30f, rm1 = -1e30f;

    // constant "ones" B fragment: column 0 of the 8-wide n-tile is all ones
    const unsigned onesB = (grp == 0) ? 0x3C003C00u : 0u;

    const char* gph = (const char*)(d_ph + ((size_t)b * MM) * CI);
    const char* ggT = (const char*)(d_gT + (size_t)b * CI * MM);

    auto copy_tile = [&](int mt, int buf) {
        const unsigned phO = buf ? PH1o : PH0o;
        const unsigned gO  = buf ? G1o : G0o;
        const char* ph = gph + (size_t)mt * 64 * CI * 2;
        #pragma unroll
        for (int it = 0; it < 2; ++it) {
            int idx = tid + it * 128;          // 0..255
            int key = idx >> 2, c = idx & 3;
            cpa16(shb + phO + key * 80 + c * 16, ph + idx * 16);
        }
        #pragma unroll
        for (int it = 0; it < 2; ++it) {
            int idx = tid + it * 128;          // 0..255
            int ci = idx >> 3, c = idx & 7;
            cpa16(shb + gO + ci * 144 + c * 16,
                  ggT + (size_t)ci * (MM * 2) + (size_t)mt * 128 + c * 16);
        }
    };

    copy_tile(0, 0);
    cpcommit();

    const unsigned lmBase = (lane & 7) * 80 + (lane >> 3) * 16;   // phi ldsm
    const unsigned lmG = (unsigned)(((lane >> 4) * 8 + (lane & 7)) * 144 +
                                    ((lane >> 3) & 1) * 16);

    for (int mt = 0; mt < TILES; ++mt) {
        const int cur = mt & 1;
        if (mt + 1 < TILES) { copy_tile(mt + 1, cur ^ 1); cpcommit(); cpwait<1>(); }
        else                { cpwait<0>(); }
        __syncthreads();

        const unsigned phA = shb + (cur ? PH1o : PH0o) + lmBase;
        const unsigned gA  = shb + (cur ? G1o : G0o) + lmG;

        // ---- S = (thH + thL) . phi^T  (2 terms, zero-C first mma) -------
        float s[8][4];
        #pragma unroll
        for (int nt = 0; nt < 8; ++nt) {
            uint4 bh = ldsm4(phA + nt * 640);
            mma16z(s[nt], aH[0], bh.x, bh.y);
            mma16(s[nt], aH[1], bh.z, bh.w);
            mma16(s[nt], aL[0], bh.x, bh.y);
            mma16(s[nt], aL[1], bh.z, bh.w);
        }

        // ---- online softmax (log2 domain) -------------------------------
        float m0 = s[0][0], m1 = s[0][2];
        #pragma unroll
        for (int nt = 0; nt < 8; ++nt) {
            m0 = fmaxf(m0, fmaxf(s[nt][0], s[nt][1]));
            m1 = fmaxf(m1, fmaxf(s[nt][2], s[nt][3]));
        }
        m0 = fmaxf(m0, __shfl_xor_sync(0xffffffffu, m0, 1));
        m0 = fmaxf(m0, __shfl_xor_sync(0xffffffffu, m0, 2));
        m1 = fmaxf(m1, __shfl_xor_sync(0xffffffffu, m1, 1));
        m1 = fmaxf(m1, __shfl_xor_sync(0xffffffffu, m1, 2));

        const float nm0 = fmaxf(rm0, m0);
        const float nm1 = fmaxf(rm1, m1);
        const float sc0 = exp2f(rm0 - nm0);
        const float sc1 = exp2f(rm1 - nm1);
        rm0 = nm0; rm1 = nm1;
        #pragma unroll
        for (int nc = 0; nc < 4; ++nc) {
            y[nc][0] *= sc0; y[nc][1] *= sc0;
            y[nc][2] *= sc1; y[nc][3] *= sc1;
        }
        y5[0] *= sc0; y5[2] *= sc1;

        // ---- P = 2^(S-m) via f16x2 MUFU;  y += P @ g; y5 += P @ ones ----
        #pragma unroll
        for (int kc = 0; kc < 4; ++kc) {
            const int nt0 = 2 * kc, nt1 = 2 * kc + 1;
            unsigned pa[4];
            pa[0] = h2ex2(pkhf2(s[nt0][0] - nm0, s[nt0][1] - nm0));
            pa[1] = h2ex2(pkhf2(s[nt0][2] - nm1, s[nt0][3] - nm1));
            pa[2] = h2ex2(pkhf2(s[nt1][0] - nm0, s[nt1][1] - nm0));
            pa[3] = h2ex2(pkhf2(s[nt1][2] - nm1, s[nt1][3] - nm1));

            uint4 h0 = ldsm4(gA + kc * 32);            // nc 0,1
            uint4 h1 = ldsm4(gA + 2304 + kc * 32);     // nc 2,3
            mma16(y[0], pa, h0.x, h0.y);
            mma16(y[1], pa, h0.z, h0.w);
            mma16(y[2], pa, h1.x, h1.y);
            mma16(y[3], pa, h1.z, h1.w);
            mma16(y5,   pa, onesB, onesB);
        }
        __syncthreads();
    }

    // row sums live in col 0 (t==0 lanes): broadcast within each group
    const float rs0 = __shfl_sync(0xffffffffu, y5[0], lane & ~3);
    const float rs1 = __shfl_sync(0xffffffffu, y5[2], lane & ~3);
    const float inv0 = 1.0f / rs0;
    const float inv1 = 1.0f / rs1;

    float* ySm = (float*)(SM + G0o);       // reuse g buffers (9216 B >= 8448)
    #pragma unroll
    for (int nc = 0; nc < 4; ++nc) {
        ySm[row0 * 33 + nc * 8 + 2 * t]           = y[nc][0] * inv0;
        ySm[row0 * 33 + nc * 8 + 2 * t + 1]       = y[nc][1] * inv0;
        ySm[(row0 + 8) * 33 + nc * 8 + 2 * t]     = y[nc][2] * inv1;
        ySm[(row0 + 8) * 33 + nc * 8 + 2 * t + 1] = y[nc][3] * inv1;
    }
    __syncthreads();

    // epilogue: out[b][c][n] = y . w_out[c] + b_out[c] + x[b][c][n]
    {
        const int row  = tid >> 1;
        const int half = tid & 1;
        float yv[32];
        #pragma unroll
        for (int i = 0; i < 32; ++i) yv[i] = ySm[row * 33 + i];
        const int n = n0b + row;
        #pragma unroll
        for (int j = 0; j < 32; ++j) {
            const int c = half * 32 + j;
            float acc = b_out[c];
            #pragma unroll
            for (int ci = 0; ci < 32; ++ci)
                acc = fmaf(woS[c * 33 + ci], yv[ci], acc);
            const size_t oi = ((size_t)(b * CC + c)) * NN + n;
            out[oi] = acc + x[oi];
        }
    }
}

// ---------------------------------------------------------------------------
extern "C" void kernel_launch(void* const* d_in, const int* in_sizes, int n_in,
                              void* d_out, int out_size)
{
    const float* x  = (const float*)d_in[0];
    const float* wt = (const float*)d_in[1];
    const float* bt = (const float*)d_in[2];
    const float* wp = (const float*)d_in[3];
    const float* bp = (const float*)d_in[4];
    const float* wg = (const float*)d_in[5];
    const float* bg = (const float*)d_in[6];
    const float* wo = (const float*)d_in[7];
    const float* bo = (const float*)d_in[8];
    float* out = (float*)d_out;

    dim3 grid(NN / 64, BB);
    proj_kernel<<<grid, 256>>>(x, wt, bt, wp, bp, wg, bg);
    attn_kernel<<<grid, 128>>>(x, wo, bo, out);
}

// round 7
// speedup vs baseline: 9.7191x; 1.1037x over previous
#include <cuda_runtime.h>
#include <cuda_fp16.h>
#include <cuda_bf16.h>

// ---------------------------------------------------------------------------
// NonlocalBlock: B=4, C=64, N=9216, Ci=32, M=4608
// Round 7: 32 query rows per warp (phi-fragment reuse across two 16-row sets),
// 128-row blocks (grid 288). f32x2-packed proj + epilogue. fp16 tensor attn.
// ---------------------------------------------------------------------------

#define BB 4
#define CC 64
#define NN 9216
#define CI 32
#define MM 4608
#define TILES (MM / 64)
#define LOG2E 1.4426950408889634f

typedef unsigned long long ull;

// scratch (__device__ globals: allocation-free rule)
__device__ __half d_thH[(size_t)BB * NN * CI];   // theta*log2e hi (fp16)
__device__ __half d_thL[(size_t)BB * NN * CI];   // theta*log2e lo (fp16)
__device__ __half d_ph [(size_t)BB * MM * CI];   // phi (fp16 rn)
__device__ __half d_gT [(size_t)BB * CI * MM];   // g transposed (fp16 rn)

// ---- f32x2 helpers --------------------------------------------------------
__device__ __forceinline__ ull pk2(float lo, float hi) {
    ull r; asm("mov.b64 %0, {%1,%2};" : "=l"(r) : "f"(lo), "f"(hi)); return r;
}
__device__ __forceinline__ void upk2(ull a, float& lo, float& hi) {
    asm("mov.b64 {%0,%1}, %2;" : "=f"(lo), "=f"(hi) : "l"(a));
}
__device__ __forceinline__ ull fma2(ull a, ull b, ull c) {
    ull d; asm("fma.rn.f32x2 %0, %1, %2, %3;" : "=l"(d) : "l"(a), "l"(b), "l"(c)); return d;
}

// ---- fp16 mma helpers -----------------------------------------------------
__device__ __forceinline__ void mma16(float* c, const unsigned* a,
                                      unsigned b0, unsigned b1) {
    asm volatile(
        "mma.sync.aligned.m16n8k16.row.col.f32.f16.f16.f32 "
        "{%0,%1,%2,%3}, {%4,%5,%6,%7}, {%8,%9}, {%0,%1,%2,%3};"
        : "+f"(c[0]), "+f"(c[1]), "+f"(c[2]), "+f"(c[3])
        : "r"(a[0]), "r"(a[1]), "r"(a[2]), "r"(a[3]), "r"(b0), "r"(b1));
}
__device__ __forceinline__ void mma16z(float* d, const unsigned* a,
                                       unsigned b0, unsigned b1) {
    asm volatile(
        "mma.sync.aligned.m16n8k16.row.col.f32.f16.f16.f32 "
        "{%0,%1,%2,%3}, {%4,%5,%6,%7}, {%8,%9}, {%10,%11,%12,%13};"
        : "=f"(d[0]), "=f"(d[1]), "=f"(d[2]), "=f"(d[3])
        : "r"(a[0]), "r"(a[1]), "r"(a[2]), "r"(a[3]), "r"(b0), "r"(b1),
          "f"(0.f), "f"(0.f), "f"(0.f), "f"(0.f));
}
__device__ __forceinline__ uint4 ldsm4(unsigned a) {
    uint4 r;
    asm volatile("ldmatrix.sync.aligned.m8n8.x4.shared.b16 {%0,%1,%2,%3}, [%4];"
                 : "=r"(r.x), "=r"(r.y), "=r"(r.z), "=r"(r.w) : "r"(a));
    return r;
}
__device__ __forceinline__ void cpa16(unsigned s, const void* g) {
    asm volatile("cp.async.ca.shared.global [%0], [%1], 16;" :: "r"(s), "l"(g));
}
__device__ __forceinline__ void cpcommit() { asm volatile("cp.async.commit_group;"); }
template <int N> __device__ __forceinline__ void cpwait() {
    asm volatile("cp.async.wait_group %0;" :: "n"(N));
}
__device__ __forceinline__ unsigned pkhf2(float lo, float hi) {
    unsigned d; asm("cvt.rn.f16x2.f32 %0, %1, %2;" : "=r"(d) : "f"(hi), "f"(lo));
    return d;
}
__device__ __forceinline__ unsigned h2ex2(unsigned x) {
    unsigned d; asm("ex2.approx.f16x2 %0, %1;" : "=r"(d) : "r"(x));
    return d;
}

// ---------------------------------------------------------------------------
// Kernel 1: projections + maxpool, f32x2-packed math.
// grid = (NN/64, BB), 256 threads (8 groups of 8 positions; lane = ci).
// ---------------------------------------------------------------------------
__global__ __launch_bounds__(256, 2)
void proj_kernel(const float* __restrict__ x,
                 const float* __restrict__ wt, const float* __restrict__ bt,
                 const float* __restrict__ wp, const float* __restrict__ bp,
                 const float* __restrict__ wg, const float* __restrict__ bg)
{
    __shared__ float xs[64][66];          // [chan][pos], conflict-free
    __shared__ float wts[64][32];
    __shared__ float wps[64][32];
    __shared__ float wgs[64][32];
    __shared__ __half gs[32][36];         // pooled g transpose buffer

    const int b  = blockIdx.y;
    const int n0 = blockIdx.x * 64;
    const int tid = threadIdx.x;

    for (int i = tid; i < CI * CC; i += 256) {
        int ci = i >> 6, c = i & 63;
        wts[c][ci] = wt[i];
        wps[c][ci] = wp[i];
        wgs[c][ci] = wg[i];
    }
    for (int i = tid; i < 64 * 64; i += 256) {
        int c = i >> 6, nl = i & 63;
        xs[c][nl] = x[((size_t)(b * CC + c)) * NN + n0 + nl];
    }
    __syncthreads();

    const int ci = tid & 31;
    const int g8 = tid >> 5;
    const int p0 = g8 * 8;

    ull at2[4], ap2[4], ag2[4];
    #pragma unroll
    for (int j = 0; j < 4; ++j) { at2[j] = 0ull; ap2[j] = 0ull; ag2[j] = 0ull; }

    #pragma unroll
    for (int cb = 0; cb < 64; cb += 8) {
        ull wt2[8], wp2[8], wg2[8];
        #pragma unroll
        for (int k = 0; k < 8; ++k) {
            float a = wts[cb + k][ci]; wt2[k] = pk2(a, a);
            float p = wps[cb + k][ci]; wp2[k] = pk2(p, p);
            float g = wgs[cb + k][ci]; wg2[k] = pk2(g, g);
        }
        #pragma unroll
        for (int k = 0; k < 8; ++k) {
            #pragma unroll
            for (int j = 0; j < 4; ++j) {
                ull xv = *(const ull*)&xs[cb + k][p0 + 2 * j];
                at2[j] = fma2(xv, wt2[k], at2[j]);
                ap2[j] = fma2(xv, wp2[k], ap2[j]);
                ag2[j] = fma2(xv, wg2[k], ag2[j]);
            }
        }
    }

    const float bth = bt[ci], bph = bp[ci], bgg = bg[ci];
    #pragma unroll
    for (int j = 0; j < 4; ++j) {
        const int n = n0 + p0 + 2 * j;
        float alo, ahi; upk2(at2[j], alo, ahi);
        const float tv0 = (alo + bth) * LOG2E;
        const float tv1 = (ahi + bth) * LOG2E;
        {
            const size_t t0 = ((size_t)(b * NN + n)) * CI + ci;
            __half h0 = __float2half_rn(tv0);
            d_thH[t0] = h0;
            d_thL[t0] = __float2half_rn(tv0 - __half2float(h0));
            __half h1 = __float2half_rn(tv1);
            d_thH[t0 + CI] = h1;
            d_thL[t0 + CI] = __float2half_rn(tv1 - __half2float(h1));
        }
        float plo, phi_; upk2(ap2[j], plo, phi_);
        const float pv = fmaxf(plo, phi_) + bph;
        const int m = n >> 1;
        d_ph[((size_t)(b * MM + m)) * CI + ci] = __float2half_rn(pv);
        float glo, ghi; upk2(ag2[j], glo, ghi);
        gs[ci][g8 * 4 + j] = __float2half_rn(fmaxf(glo, ghi) + bgg);
    }
    __syncthreads();

    // coalesced gT write: 32 ci rows x 32 m (64B per row)
    for (int i = tid; i < 32 * 32; i += 256) {
        const int cr = i >> 5, ml = i & 31;
        d_gT[((size_t)(b * CI + cr)) * MM + (n0 >> 1) + ml] = gs[cr][ml];
    }
}

// ---------------------------------------------------------------------------
// smem byte offsets
// ---------------------------------------------------------------------------
#define PH0o 0u           // phi buf0: 64 keys x 80B rows = 5120
#define PH1o 5120u
#define G0o  10240u       // gT buf0: 32 ci x 144B rows = 4608
#define G1o  14848u
#define WOo  19456u       // paired w_out: 32 pairs x 33 x float2 = 8448
#define SMSZ 27904u

// ---------------------------------------------------------------------------
// Kernel 2: flash attention + out-proj + residual.
// grid = (NN/128, BB), 128 threads (4 warps x 32 query rows in 2 sets).
// ---------------------------------------------------------------------------
__global__ __launch_bounds__(128, 2)
void attn_kernel(const float* __restrict__ x,
                 const float* __restrict__ w_out,
                 const float* __restrict__ b_out,
                 float* __restrict__ out)
{
    __shared__ __align__(16) unsigned char SM[SMSZ];
    const unsigned shb = (unsigned)__cvta_generic_to_shared(SM);

    const int b    = blockIdx.y;
    const int n0b  = blockIdx.x * 128;
    const int tid  = threadIdx.x;
    const int warp = tid >> 5;
    const int lane = tid & 31;
    const int grp  = lane >> 2;
    const int t    = lane & 3;

    // w_out in channel-paired layout for f32x2 epilogue
    {
        float* woF = (float*)(SM + WOo);
        for (int i = tid; i < CC * CI; i += 128) {
            int c = i >> 5, ci = i & 31;
            woF[((c >> 1) * 33 + ci) * 2 + (c & 1)] = w_out[i];
        }
    }

    // ---- theta A fragments: two 16-row sets per warp --------------------
    const int r0 = warp * 32 + grp;        // set0 rows r0, r0+8
    const int r1 = r0 + 16;                // set1 rows r1, r1+8
    unsigned aH0[2][4], aL0[2][4], aH1[2][4], aL1[2][4];
    {
        const __half* thH = d_thH + ((size_t)(b * NN + n0b)) * CI;
        const __half* thL = d_thL + ((size_t)(b * NN + n0b)) * CI;
        #pragma unroll
        for (int ch = 0; ch < 2; ++ch) {
            const int c0 = ch * 16 + 2 * t;
            aH0[ch][0] = *(const unsigned*)(thH + (size_t)r0 * CI + c0);
            aH0[ch][1] = *(const unsigned*)(thH + (size_t)(r0 + 8) * CI + c0);
            aH0[ch][2] = *(const unsigned*)(thH + (size_t)r0 * CI + c0 + 8);
            aH0[ch][3] = *(const unsigned*)(thH + (size_t)(r0 + 8) * CI + c0 + 8);
            aL0[ch][0] = *(const unsigned*)(thL + (size_t)r0 * CI + c0);
            aL0[ch][1] = *(const unsigned*)(thL + (size_t)(r0 + 8) * CI + c0);
            aL0[ch][2] = *(const unsigned*)(thL + (size_t)r0 * CI + c0 + 8);
            aL0[ch][3] = *(const unsigned*)(thL + (size_t)(r0 + 8) * CI + c0 + 8);
            aH1[ch][0] = *(const unsigned*)(thH + (size_t)r1 * CI + c0);
            aH1[ch][1] = *(const unsigned*)(thH + (size_t)(r1 + 8) * CI + c0);
            aH1[ch][2] = *(const unsigned*)(thH + (size_t)r1 * CI + c0 + 8);
            aH1[ch][3] = *(const unsigned*)(thH + (size_t)(r1 + 8) * CI + c0 + 8);
            aL1[ch][0] = *(const unsigned*)(thL + (size_t)r1 * CI + c0);
            aL1[ch][1] = *(const unsigned*)(thL + (size_t)(r1 + 8) * CI + c0);
            aL1[ch][2] = *(const unsigned*)(thL + (size_t)r1 * CI + c0 + 8);
            aL1[ch][3] = *(const unsigned*)(thL + (size_t)(r1 + 8) * CI + c0 + 8);
        }
    }

    float y0[4][4], y1[4][4];
    #pragma unroll
    for (int i = 0; i < 4; ++i)
        #pragma unroll
        for (int j = 0; j < 4; ++j) { y0[i][j] = 0.f; y1[i][j] = 0.f; }
    float y5_0[4] = {0.f, 0.f, 0.f, 0.f};
    float y5_1[4] = {0.f, 0.f, 0.f, 0.f};
    float rm00 = -1e30f, rm01 = -1e30f, rm10 = -1e30f, rm11 = -1e30f;

    const unsigned onesB = (grp == 0) ? 0x3C003C00u : 0u;

    const char* gph = (const char*)(d_ph + ((size_t)b * MM) * CI);
    const char* ggT = (const char*)(d_gT + (size_t)b * CI * MM);

    auto copy_tile = [&](int mt, int buf) {
        const unsigned phO = buf ? PH1o : PH0o;
        const unsigned gO  = buf ? G1o : G0o;
        const char* ph = gph + (size_t)mt * 64 * CI * 2;
        #pragma unroll
        for (int it = 0; it < 2; ++it) {
            int idx = tid + it * 128;          // 0..255
            int key = idx >> 2, c = idx & 3;
            cpa16(shb + phO + key * 80 + c * 16, ph + idx * 16);
        }
        #pragma unroll
        for (int it = 0; it < 2; ++it) {
            int idx = tid + it * 128;          // 0..255
            int ci = idx >> 3, c = idx & 7;
            cpa16(shb + gO + ci * 144 + c * 16,
                  ggT + (size_t)ci * (MM * 2) + (size_t)mt * 128 + c * 16);
        }
    };

    copy_tile(0, 0);
    cpcommit();

    const unsigned lmBase = (lane & 7) * 80 + (lane >> 3) * 16;   // phi ldsm
    const unsigned lmG = (unsigned)(((lane >> 4) * 8 + (lane & 7)) * 144 +
                                    ((lane >> 3) & 1) * 16);

    for (int mt = 0; mt < TILES; ++mt) {
        const int cur = mt & 1;
        if (mt + 1 < TILES) { copy_tile(mt + 1, cur ^ 1); cpcommit(); cpwait<1>(); }
        else                { cpwait<0>(); }
        __syncthreads();

        const unsigned phA = shb + (cur ? PH1o : PH0o) + lmBase;
        const unsigned gA  = shb + (cur ? G1o : G0o) + lmG;

        // phi fragments once per tile, reused by both row sets
        uint4 bh[8];
        #pragma unroll
        for (int nt = 0; nt < 8; ++nt) bh[nt] = ldsm4(phA + nt * 640);

        unsigned pa0[4][4], pa1[4][4];
        float s[8][4];

        // ================= row set 0 =================
        #pragma unroll
        for (int nt = 0; nt < 8; ++nt) {
            mma16z(s[nt], aH0[0], bh[nt].x, bh[nt].y);
            mma16(s[nt], aH0[1], bh[nt].z, bh[nt].w);
            mma16(s[nt], aL0[0], bh[nt].x, bh[nt].y);
            mma16(s[nt], aL0[1], bh[nt].z, bh[nt].w);
        }
        {
            float m0 = s[0][0], m1 = s[0][2];
            #pragma unroll
            for (int nt = 0; nt < 8; ++nt) {
                m0 = fmaxf(m0, fmaxf(s[nt][0], s[nt][1]));
                m1 = fmaxf(m1, fmaxf(s[nt][2], s[nt][3]));
            }
            m0 = fmaxf(m0, __shfl_xor_sync(0xffffffffu, m0, 1));
            m0 = fmaxf(m0, __shfl_xor_sync(0xffffffffu, m0, 2));
            m1 = fmaxf(m1, __shfl_xor_sync(0xffffffffu, m1, 1));
            m1 = fmaxf(m1, __shfl_xor_sync(0xffffffffu, m1, 2));
            const float nm0 = fmaxf(rm00, m0);
            const float nm1 = fmaxf(rm01, m1);
            const float sc0 = exp2f(rm00 - nm0);
            const float sc1 = exp2f(rm01 - nm1);
            rm00 = nm0; rm01 = nm1;
            #pragma unroll
            for (int nc = 0; nc < 4; ++nc) {
                y0[nc][0] *= sc0; y0[nc][1] *= sc0;
                y0[nc][2] *= sc1; y0[nc][3] *= sc1;
            }
            y5_0[0] *= sc0; y5_0[2] *= sc1;
            #pragma unroll
            for (int kc = 0; kc < 4; ++kc) {
                const int n0t = 2 * kc, n1t = 2 * kc + 1;
                pa0[kc][0] = h2ex2(pkhf2(s[n0t][0] - nm0, s[n0t][1] - nm0));
                pa0[kc][1] = h2ex2(pkhf2(s[n0t][2] - nm1, s[n0t][3] - nm1));
                pa0[kc][2] = h2ex2(pkhf2(s[n1t][0] - nm0, s[n1t][1] - nm0));
                pa0[kc][3] = h2ex2(pkhf2(s[n1t][2] - nm1, s[n1t][3] - nm1));
            }
        }

        // ================= row set 1 =================
        #pragma unroll
        for (int nt = 0; nt < 8; ++nt) {
            mma16z(s[nt], aH1[0], bh[nt].x, bh[nt].y);
            mma16(s[nt], aH1[1], bh[nt].z, bh[nt].w);
            mma16(s[nt], aL1[0], bh[nt].x, bh[nt].y);
            mma16(s[nt], aL1[1], bh[nt].z, bh[nt].w);
        }
        {
            float m0 = s[0][0], m1 = s[0][2];
            #pragma unroll
            for (int nt = 0; nt < 8; ++nt) {
                m0 = fmaxf(m0, fmaxf(s[nt][0], s[nt][1]));
                m1 = fmaxf(m1, fmaxf(s[nt][2], s[nt][3]));
            }
            m0 = fmaxf(m0, __shfl_xor_sync(0xffffffffu, m0, 1));
            m0 = fmaxf(m0, __shfl_xor_sync(0xffffffffu, m0, 2));
            m1 = fmaxf(m1, __shfl_xor_sync(0xffffffffu, m1, 1));
            m1 = fmaxf(m1, __shfl_xor_sync(0xffffffffu, m1, 2));
            const float nm0 = fmaxf(rm10, m0);
            const float nm1 = fmaxf(rm11, m1);
            const float sc0 = exp2f(rm10 - nm0);
            const float sc1 = exp2f(rm11 - nm1);
            rm10 = nm0; rm11 = nm1;
            #pragma unroll
            for (int nc = 0; nc < 4; ++nc) {
                y1[nc][0] *= sc0; y1[nc][1] *= sc0;
                y1[nc][2] *= sc1; y1[nc][3] *= sc1;
            }
            y5_1[0] *= sc0; y5_1[2] *= sc1;
            #pragma unroll
            for (int kc = 0; kc < 4; ++kc) {
                const int n0t = 2 * kc, n1t = 2 * kc + 1;
                pa1[kc][0] = h2ex2(pkhf2(s[n0t][0] - nm0, s[n0t][1] - nm0));
                pa1[kc][1] = h2ex2(pkhf2(s[n0t][2] - nm1, s[n0t][3] - nm1));
                pa1[kc][2] = h2ex2(pkhf2(s[n1t][0] - nm0, s[n1t][1] - nm0));
                pa1[kc][3] = h2ex2(pkhf2(s[n1t][2] - nm1, s[n1t][3] - nm1));
            }
        }

        // ================= P @ g (both sets share g frags) ===============
        #pragma unroll
        for (int kc = 0; kc < 4; ++kc) {
            uint4 h0 = ldsm4(gA + kc * 32);            // nc 0,1
            uint4 h1 = ldsm4(gA + 2304 + kc * 32);     // nc 2,3
            mma16(y0[0], pa0[kc], h0.x, h0.y);
            mma16(y0[1], pa0[kc], h0.z, h0.w);
            mma16(y0[2], pa0[kc], h1.x, h1.y);
            mma16(y0[3], pa0[kc], h1.z, h1.w);
            mma16(y1[0], pa1[kc], h0.x, h0.y);
            mma16(y1[1], pa1[kc], h0.z, h0.w);
            mma16(y1[2], pa1[kc], h1.x, h1.y);
            mma16(y1[3], pa1[kc], h1.z, h1.w);
            mma16(y5_0, pa0[kc], onesB, onesB);
            mma16(y5_1, pa1[kc], onesB, onesB);
        }
        __syncthreads();
    }

    // row sums: col 0 lives on t==0 lanes of each group
    const float rs00 = __shfl_sync(0xffffffffu, y5_0[0], lane & ~3);
    const float rs01 = __shfl_sync(0xffffffffu, y5_0[2], lane & ~3);
    const float rs10 = __shfl_sync(0xffffffffu, y5_1[0], lane & ~3);
    const float rs11 = __shfl_sync(0xffffffffu, y5_1[2], lane & ~3);
    const float i00 = 1.0f / rs00, i01 = 1.0f / rs01;
    const float i10 = 1.0f / rs10, i11 = 1.0f / rs11;

    float* ySm = (float*)SM;               // 128 x 33 floats = 16896 B
    #pragma unroll
    for (int nc = 0; nc < 4; ++nc) {
        ySm[r0 * 33 + nc * 8 + 2 * t]            = y0[nc][0] * i00;
        ySm[r0 * 33 + nc * 8 + 2 * t + 1]        = y0[nc][1] * i00;
        ySm[(r0 + 8) * 33 + nc * 8 + 2 * t]      = y0[nc][2] * i01;
        ySm[(r0 + 8) * 33 + nc * 8 + 2 * t + 1]  = y0[nc][3] * i01;
        ySm[r1 * 33 + nc * 8 + 2 * t]            = y1[nc][0] * i10;
        ySm[r1 * 33 + nc * 8 + 2 * t + 1]        = y1[nc][1] * i10;
        ySm[(r1 + 8) * 33 + nc * 8 + 2 * t]      = y1[nc][2] * i11;
        ySm[(r1 + 8) * 33 + nc * 8 + 2 * t + 1]  = y1[nc][3] * i11;
    }
    __syncthreads();

    // epilogue: one thread per query row, f32x2 over channel pairs
    {
        const int row = tid;
        const int n = n0b + row;
        float yv[32];
        #pragma unroll
        for (int i = 0; i < 32; ++i) yv[i] = ySm[row * 33 + i];
        ull yv2[32];
        #pragma unroll
        for (int i = 0; i < 32; ++i) yv2[i] = pk2(yv[i], yv[i]);
        const ull* wo2 = (const ull*)(SM + WOo);
        #pragma unroll 4
        for (int p = 0; p < 32; ++p) {
            ull acc = pk2(b_out[2 * p], b_out[2 * p + 1]);
            #pragma unroll
            for (int ci = 0; ci < 32; ++ci)
                acc = fma2(yv2[ci], wo2[p * 33 + ci], acc);
            float lo, hi; upk2(acc, lo, hi);
            const size_t o0 = ((size_t)(b * CC + 2 * p)) * NN + n;
            out[o0]      = lo + x[o0];
            out[o0 + NN] = hi + x[o0 + NN];
        }
    }
}

// ---------------------------------------------------------------------------
extern "C" void kernel_launch(void* const* d_in, const int* in_sizes, int n_in,
                              void* d_out, int out_size)
{
    const float* x  = (const float*)d_in[0];
    const float* wt = (const float*)d_in[1];
    const float* bt = (const float*)d_in[2];
    const float* wp = (const float*)d_in[3];
    const float* bp = (const float*)d_in[4];
    const float* wg = (const float*)d_in[5];
    const float* bg = (const float*)d_in[6];
    const float* wo = (const float*)d_in[7];
    const float* bo = (const float*)d_in[8];
    float* out = (float*)d_out;

    proj_kernel<<<dim3(NN / 64, BB), 256>>>(x, wt, bt, wp, bp, wg, bg);
    attn_kernel<<<dim3(NN / 128, BB), 128>>>(x, wo, bo, out);
}